// round 1
// baseline (speedup 1.0000x reference)
#include <cuda_runtime.h>
#include <math.h>

#define N_NODES 50000
#define E_EDGES 600000
#define H 128
#define ED 64
#define EPB 16   // edges per block  (E_EDGES % EPB == 0)
#define NPB 16   // nodes per block  (N_NODES % NPB == 0)

// Scratch (device globals: no allocation allowed)
__device__ float g_h[(size_t)N_NODES * H];    // LN1(x)
__device__ float g_agg[(size_t)N_NODES * H];  // segment sum of edge_repr
__device__ float g_deg[N_NODES];              // degree

__device__ __forceinline__ float gelu_exact(float v) {
    return 0.5f * v * (1.0f + erff(v * 0.70710678118654752440f));
}

// ---------------------------------------------------------------------------
__global__ void zero_kernel() {
    size_t i = (size_t)blockIdx.x * blockDim.x + threadIdx.x;
    size_t stride = (size_t)gridDim.x * blockDim.x;
    size_t tot = (size_t)N_NODES * H;
    for (size_t k = i; k < tot; k += stride) g_agg[k] = 0.0f;
    for (size_t k = i; k < N_NODES; k += stride) g_deg[k] = 0.0f;
}

// ---------------------------------------------------------------------------
// LN1: one warp per node.
__global__ void ln1_kernel(const float* __restrict__ x,
                           const float* __restrict__ g,
                           const float* __restrict__ b) {
    int warp = (int)((blockIdx.x * blockDim.x + threadIdx.x) >> 5);
    int lane = threadIdx.x & 31;
    if (warp >= N_NODES) return;
    float4 v = *(const float4*)(x + (size_t)warp * H + 4 * lane);
    float s = v.x + v.y + v.z + v.w;
    #pragma unroll
    for (int o = 16; o; o >>= 1) s += __shfl_xor_sync(0xffffffffu, s, o);
    float mu = s * (1.0f / H);
    float dx = v.x - mu, dy = v.y - mu, dz = v.z - mu, dw = v.w - mu;
    float q = dx * dx + dy * dy + dz * dz + dw * dw;
    #pragma unroll
    for (int o = 16; o; o >>= 1) q += __shfl_xor_sync(0xffffffffu, q, o);
    float rstd = rsqrtf(q * (1.0f / H) + 1e-5f);
    float4 gg = *(const float4*)(g + 4 * lane);
    float4 bb = *(const float4*)(b + 4 * lane);
    float4 r;
    r.x = dx * rstd * gg.x + bb.x;
    r.y = dy * rstd * gg.y + bb.y;
    r.z = dz * rstd * gg.z + bb.z;
    r.w = dw * rstd * gg.w + bb.w;
    *(float4*)(g_h + (size_t)warp * H + 4 * lane) = r;
}

// ---------------------------------------------------------------------------
// Edge kernel: block = 128 threads (4 warps). Warp handles 4 edges, lane
// handles 4 output columns. One LDG.128 of a weight row serves 4 edges x 4
// cols = 16 lane-MACs -> weight traffic amortized (L1-resident weights).
__global__ __launch_bounds__(128) void edge_kernel(
    const int* __restrict__ esrc, const int* __restrict__ edst,
    const float* __restrict__ emb,
    const float* __restrict__ Wm1, const float* __restrict__ bm1,
    const float* __restrict__ Wm2, const float* __restrict__ bm2,
    const float* __restrict__ Wg1, const float* __restrict__ bg1,
    const float* __restrict__ Wg2, const float* __restrict__ bg2,
    float* __restrict__ out_edge)
{
    __shared__ float s_in[EPB][320];   // [hd(128) | hs(128) | e(64)]
    __shared__ float s_t1[EPB][H];
    __shared__ int s_src[EPB], s_dst[EPB];

    int tid = threadIdx.x;
    int e_base = blockIdx.x * EPB;

    if (tid < EPB) {
        int sdx = esrc[e_base + tid];
        int ddx = edst[e_base + tid];
        s_src[tid] = sdx;
        s_dst[tid] = ddx;
        atomicAdd(&g_deg[ddx], 1.0f);
    }
    __syncthreads();

    // Stage inputs: EPB edges x 80 float4
    for (int i = tid; i < EPB * 80; i += 128) {
        int e = i / 80, c = i % 80;
        float4 v;
        if (c < 32)       v = *(const float4*)(g_h + (size_t)s_dst[e] * H + c * 4);
        else if (c < 64)  v = *(const float4*)(g_h + (size_t)s_src[e] * H + (c - 32) * 4);
        else              v = *(const float4*)(emb + (size_t)(e_base + e) * ED + (c - 64) * 4);
        *(float4*)(&s_in[e][c * 4]) = v;
    }
    __syncthreads();

    int warp = tid >> 5, lane = tid & 31;
    int e0 = warp * 4;
    int j0 = lane * 4;

    // ---- GEMM m1: t1 = gelu([hs||e] @ Wm1 + bm1), K=192 ----
    float4 acc[4];
    {
        float4 bb = *(const float4*)(bm1 + j0);
        #pragma unroll
        for (int e = 0; e < 4; e++) acc[e] = bb;
    }
    for (int k = 0; k < 192; k += 4) {
        float4 w0 = *(const float4*)(Wm1 + (size_t)(k + 0) * H + j0);
        float4 w1 = *(const float4*)(Wm1 + (size_t)(k + 1) * H + j0);
        float4 w2 = *(const float4*)(Wm1 + (size_t)(k + 2) * H + j0);
        float4 w3 = *(const float4*)(Wm1 + (size_t)(k + 3) * H + j0);
        #pragma unroll
        for (int e = 0; e < 4; e++) {
            float4 s = *(const float4*)(&s_in[e0 + e][128 + k]);
            acc[e].x = fmaf(s.x, w0.x, acc[e].x); acc[e].y = fmaf(s.x, w0.y, acc[e].y);
            acc[e].z = fmaf(s.x, w0.z, acc[e].z); acc[e].w = fmaf(s.x, w0.w, acc[e].w);
            acc[e].x = fmaf(s.y, w1.x, acc[e].x); acc[e].y = fmaf(s.y, w1.y, acc[e].y);
            acc[e].z = fmaf(s.y, w1.z, acc[e].z); acc[e].w = fmaf(s.y, w1.w, acc[e].w);
            acc[e].x = fmaf(s.z, w2.x, acc[e].x); acc[e].y = fmaf(s.z, w2.y, acc[e].y);
            acc[e].z = fmaf(s.z, w2.z, acc[e].z); acc[e].w = fmaf(s.z, w2.w, acc[e].w);
            acc[e].x = fmaf(s.w, w3.x, acc[e].x); acc[e].y = fmaf(s.w, w3.y, acc[e].y);
            acc[e].z = fmaf(s.w, w3.z, acc[e].z); acc[e].w = fmaf(s.w, w3.w, acc[e].w);
        }
    }
    #pragma unroll
    for (int e = 0; e < 4; e++) {
        float4 t;
        t.x = gelu_exact(acc[e].x); t.y = gelu_exact(acc[e].y);
        t.z = gelu_exact(acc[e].z); t.w = gelu_exact(acc[e].w);
        *(float4*)(&s_t1[e0 + e][j0]) = t;
    }
    __syncwarp();

    // ---- GEMM m2: msg = t1 @ Wm2 + bm2, K=128 ----
    float4 msg[4];
    {
        float4 bb = *(const float4*)(bm2 + j0);
        #pragma unroll
        for (int e = 0; e < 4; e++) msg[e] = bb;
    }
    for (int k = 0; k < 128; k += 4) {
        float4 w0 = *(const float4*)(Wm2 + (size_t)(k + 0) * H + j0);
        float4 w1 = *(const float4*)(Wm2 + (size_t)(k + 1) * H + j0);
        float4 w2 = *(const float4*)(Wm2 + (size_t)(k + 2) * H + j0);
        float4 w3 = *(const float4*)(Wm2 + (size_t)(k + 3) * H + j0);
        #pragma unroll
        for (int e = 0; e < 4; e++) {
            float4 s = *(const float4*)(&s_t1[e0 + e][k]);
            msg[e].x = fmaf(s.x, w0.x, msg[e].x); msg[e].y = fmaf(s.x, w0.y, msg[e].y);
            msg[e].z = fmaf(s.x, w0.z, msg[e].z); msg[e].w = fmaf(s.x, w0.w, msg[e].w);
            msg[e].x = fmaf(s.y, w1.x, msg[e].x); msg[e].y = fmaf(s.y, w1.y, msg[e].y);
            msg[e].z = fmaf(s.y, w1.z, msg[e].z); msg[e].w = fmaf(s.y, w1.w, msg[e].w);
            msg[e].x = fmaf(s.z, w2.x, msg[e].x); msg[e].y = fmaf(s.z, w2.y, msg[e].y);
            msg[e].z = fmaf(s.z, w2.z, msg[e].z); msg[e].w = fmaf(s.z, w2.w, msg[e].w);
            msg[e].x = fmaf(s.w, w3.x, msg[e].x); msg[e].y = fmaf(s.w, w3.y, msg[e].y);
            msg[e].z = fmaf(s.w, w3.z, msg[e].z); msg[e].w = fmaf(s.w, w3.w, msg[e].w);
        }
    }

    // ---- GEMM g1: u = gelu([hd||hs||e] @ Wg1 + bg1), K=320 ----
    float4 gac[4];
    {
        float4 bb = *(const float4*)(bg1 + j0);
        #pragma unroll
        for (int e = 0; e < 4; e++) gac[e] = bb;
    }
    for (int k = 0; k < 320; k += 4) {
        float4 w0 = *(const float4*)(Wg1 + (size_t)(k + 0) * H + j0);
        float4 w1 = *(const float4*)(Wg1 + (size_t)(k + 1) * H + j0);
        float4 w2 = *(const float4*)(Wg1 + (size_t)(k + 2) * H + j0);
        float4 w3 = *(const float4*)(Wg1 + (size_t)(k + 3) * H + j0);
        #pragma unroll
        for (int e = 0; e < 4; e++) {
            float4 s = *(const float4*)(&s_in[e0 + e][k]);
            gac[e].x = fmaf(s.x, w0.x, gac[e].x); gac[e].y = fmaf(s.x, w0.y, gac[e].y);
            gac[e].z = fmaf(s.x, w0.z, gac[e].z); gac[e].w = fmaf(s.x, w0.w, gac[e].w);
            gac[e].x = fmaf(s.y, w1.x, gac[e].x); gac[e].y = fmaf(s.y, w1.y, gac[e].y);
            gac[e].z = fmaf(s.y, w1.z, gac[e].z); gac[e].w = fmaf(s.y, w1.w, gac[e].w);
            gac[e].x = fmaf(s.z, w2.x, gac[e].x); gac[e].y = fmaf(s.z, w2.y, gac[e].y);
            gac[e].z = fmaf(s.z, w2.z, gac[e].z); gac[e].w = fmaf(s.z, w2.w, gac[e].w);
            gac[e].x = fmaf(s.w, w3.x, gac[e].x); gac[e].y = fmaf(s.w, w3.y, gac[e].y);
            gac[e].z = fmaf(s.w, w3.z, gac[e].z); gac[e].w = fmaf(s.w, w3.w, gac[e].w);
        }
    }

    // ---- gate = sigmoid(gelu(u) @ Wg2 + bg2) ----
    float4 wg = *(const float4*)(Wg2 + j0);
    float bg2s = bg2[0];
    float gate[4];
    #pragma unroll
    for (int e = 0; e < 4; e++) {
        float gx = gelu_exact(gac[e].x), gy = gelu_exact(gac[e].y);
        float gz = gelu_exact(gac[e].z), gw = gelu_exact(gac[e].w);
        float p = gx * wg.x + gy * wg.y + gz * wg.z + gw * wg.w;
        #pragma unroll
        for (int o = 16; o; o >>= 1) p += __shfl_xor_sync(0xffffffffu, p, o);
        gate[e] = 1.0f / (1.0f + expf(-(p + bg2s)));
    }

    // ---- edge_repr = gate * msg; write + scatter-add ----
    #pragma unroll
    for (int e = 0; e < 4; e++) {
        float4 r;
        r.x = gate[e] * msg[e].x; r.y = gate[e] * msg[e].y;
        r.z = gate[e] * msg[e].z; r.w = gate[e] * msg[e].w;
        size_t eg = (size_t)(e_base + e0 + e);
        *(float4*)(out_edge + eg * H + j0) = r;
        float* ag = g_agg + (size_t)s_dst[e0 + e] * H + j0;
        atomicAdd(ag + 0, r.x); atomicAdd(ag + 1, r.y);
        atomicAdd(ag + 2, r.z); atomicAdd(ag + 3, r.w);
    }
}

// ---------------------------------------------------------------------------
// Node kernel: update + residual + LN2 + FFN + residual.
// Block = 128 threads (4 warps). Warp owns 4 nodes; all phases warp-local.
__global__ __launch_bounds__(128) void node_kernel(
    const float* __restrict__ x,
    const float* __restrict__ Wself, const float* __restrict__ bself,
    const float* __restrict__ Wagg,  const float* __restrict__ bagg,
    const float* __restrict__ ln2g,  const float* __restrict__ ln2b,
    const float* __restrict__ Wf1,   const float* __restrict__ bf1,
    const float* __restrict__ Wf2,   const float* __restrict__ bf2,
    float* __restrict__ out_node)
{
    __shared__ float s_h[NPB][H];
    __shared__ float s_a[NPB][H];     // agg/deg, then reused for ffn_in
    __shared__ float s_t[NPB][2 * H]; // gelu(f1) activations

    int tid = threadIdx.x, warp = tid >> 5, lane = tid & 31;
    int nb = blockIdx.x * NPB;
    int n0 = warp * 4;
    int j0 = lane * 4;

    // Stage h and agg (per-warp for its own 4 nodes)
    for (int i = lane; i < 4 * 32; i += 32) {
        int e = i >> 5, c = i & 31;
        int n = nb + n0 + e;
        *(float4*)(&s_h[n0 + e][c * 4]) = *(const float4*)(g_h + (size_t)n * H + c * 4);
        float invd = 1.0f / fmaxf(g_deg[n], 1.0f);
        float4 a = *(const float4*)(g_agg + (size_t)n * H + c * 4);
        a.x *= invd; a.y *= invd; a.z *= invd; a.w *= invd;
        *(float4*)(&s_a[n0 + e][c * 4]) = a;
    }
    __syncwarp();

    // update = h@Wself + agg@Wagg + bself + bagg; out = x + update
    float4 o[4];
    {
        float4 b1 = *(const float4*)(bself + j0);
        float4 b2 = *(const float4*)(bagg + j0);
        float4 bb; bb.x = b1.x + b2.x; bb.y = b1.y + b2.y; bb.z = b1.z + b2.z; bb.w = b1.w + b2.w;
        #pragma unroll
        for (int e = 0; e < 4; e++) o[e] = bb;
    }
    for (int k = 0; k < 128; k += 2) {
        float4 wa0 = *(const float4*)(Wself + (size_t)(k + 0) * H + j0);
        float4 wa1 = *(const float4*)(Wself + (size_t)(k + 1) * H + j0);
        float4 wb0 = *(const float4*)(Wagg + (size_t)(k + 0) * H + j0);
        float4 wb1 = *(const float4*)(Wagg + (size_t)(k + 1) * H + j0);
        #pragma unroll
        for (int e = 0; e < 4; e++) {
            float h0 = s_h[n0 + e][k], h1 = s_h[n0 + e][k + 1];
            float a0 = s_a[n0 + e][k], a1 = s_a[n0 + e][k + 1];
            o[e].x = fmaf(h0, wa0.x, o[e].x); o[e].y = fmaf(h0, wa0.y, o[e].y);
            o[e].z = fmaf(h0, wa0.z, o[e].z); o[e].w = fmaf(h0, wa0.w, o[e].w);
            o[e].x = fmaf(h1, wa1.x, o[e].x); o[e].y = fmaf(h1, wa1.y, o[e].y);
            o[e].z = fmaf(h1, wa1.z, o[e].z); o[e].w = fmaf(h1, wa1.w, o[e].w);
            o[e].x = fmaf(a0, wb0.x, o[e].x); o[e].y = fmaf(a0, wb0.y, o[e].y);
            o[e].z = fmaf(a0, wb0.z, o[e].z); o[e].w = fmaf(a0, wb0.w, o[e].w);
            o[e].x = fmaf(a1, wb1.x, o[e].x); o[e].y = fmaf(a1, wb1.y, o[e].y);
            o[e].z = fmaf(a1, wb1.z, o[e].z); o[e].w = fmaf(a1, wb1.w, o[e].w);
        }
    }
    #pragma unroll
    for (int e = 0; e < 4; e++) {
        float4 xv = *(const float4*)(x + (size_t)(nb + n0 + e) * H + j0);
        o[e].x += xv.x; o[e].y += xv.y; o[e].z += xv.z; o[e].w += xv.w;
    }

    // LN2 -> s_a (reused)
    {
        float4 gg = *(const float4*)(ln2g + j0);
        float4 bb = *(const float4*)(ln2b + j0);
        #pragma unroll
        for (int e = 0; e < 4; e++) {
            float s = o[e].x + o[e].y + o[e].z + o[e].w;
            #pragma unroll
            for (int off = 16; off; off >>= 1) s += __shfl_xor_sync(0xffffffffu, s, off);
            float mu = s * (1.0f / H);
            float dx = o[e].x - mu, dy = o[e].y - mu, dz = o[e].z - mu, dw = o[e].w - mu;
            float q = dx * dx + dy * dy + dz * dz + dw * dw;
            #pragma unroll
            for (int off = 16; off; off >>= 1) q += __shfl_xor_sync(0xffffffffu, q, off);
            float rstd = rsqrtf(q * (1.0f / H) + 1e-5f);
            float4 f;
            f.x = dx * rstd * gg.x + bb.x; f.y = dy * rstd * gg.y + bb.y;
            f.z = dz * rstd * gg.z + bb.z; f.w = dw * rstd * gg.w + bb.w;
            *(float4*)(&s_a[n0 + e][j0]) = f;
        }
    }
    __syncwarp();

    // FFN layer 1: [H] -> [2H], lane owns 8 columns
    int j8 = lane * 8;
    float4 fA[4], fB[4];
    {
        float4 bA = *(const float4*)(bf1 + j8);
        float4 bB = *(const float4*)(bf1 + j8 + 4);
        #pragma unroll
        for (int e = 0; e < 4; e++) { fA[e] = bA; fB[e] = bB; }
    }
    #pragma unroll 2
    for (int k = 0; k < 128; k++) {
        float4 wA = *(const float4*)(Wf1 + (size_t)k * 256 + j8);
        float4 wB = *(const float4*)(Wf1 + (size_t)k * 256 + j8 + 4);
        #pragma unroll
        for (int e = 0; e < 4; e++) {
            float s = s_a[n0 + e][k];
            fA[e].x = fmaf(s, wA.x, fA[e].x); fA[e].y = fmaf(s, wA.y, fA[e].y);
            fA[e].z = fmaf(s, wA.z, fA[e].z); fA[e].w = fmaf(s, wA.w, fA[e].w);
            fB[e].x = fmaf(s, wB.x, fB[e].x); fB[e].y = fmaf(s, wB.y, fB[e].y);
            fB[e].z = fmaf(s, wB.z, fB[e].z); fB[e].w = fmaf(s, wB.w, fB[e].w);
        }
    }
    #pragma unroll
    for (int e = 0; e < 4; e++) {
        float4 tA, tB;
        tA.x = gelu_exact(fA[e].x); tA.y = gelu_exact(fA[e].y);
        tA.z = gelu_exact(fA[e].z); tA.w = gelu_exact(fA[e].w);
        tB.x = gelu_exact(fB[e].x); tB.y = gelu_exact(fB[e].y);
        tB.z = gelu_exact(fB[e].z); tB.w = gelu_exact(fB[e].w);
        *(float4*)(&s_t[n0 + e][j8]) = tA;
        *(float4*)(&s_t[n0 + e][j8 + 4]) = tB;
    }
    __syncwarp();

    // FFN layer 2: [2H] -> [H], + residual, write out
    float4 u[4];
    {
        float4 bb = *(const float4*)(bf2 + j0);
        #pragma unroll
        for (int e = 0; e < 4; e++) u[e] = bb;
    }
    for (int k = 0; k < 256; k += 4) {
        float4 w0 = *(const float4*)(Wf2 + (size_t)(k + 0) * H + j0);
        float4 w1 = *(const float4*)(Wf2 + (size_t)(k + 1) * H + j0);
        float4 w2 = *(const float4*)(Wf2 + (size_t)(k + 2) * H + j0);
        float4 w3 = *(const float4*)(Wf2 + (size_t)(k + 3) * H + j0);
        #pragma unroll
        for (int e = 0; e < 4; e++) {
            float4 s = *(const float4*)(&s_t[n0 + e][k]);
            u[e].x = fmaf(s.x, w0.x, u[e].x); u[e].y = fmaf(s.x, w0.y, u[e].y);
            u[e].z = fmaf(s.x, w0.z, u[e].z); u[e].w = fmaf(s.x, w0.w, u[e].w);
            u[e].x = fmaf(s.y, w1.x, u[e].x); u[e].y = fmaf(s.y, w1.y, u[e].y);
            u[e].z = fmaf(s.y, w1.z, u[e].z); u[e].w = fmaf(s.y, w1.w, u[e].w);
            u[e].x = fmaf(s.z, w2.x, u[e].x); u[e].y = fmaf(s.z, w2.y, u[e].y);
            u[e].z = fmaf(s.z, w2.z, u[e].z); u[e].w = fmaf(s.z, w2.w, u[e].w);
            u[e].x = fmaf(s.w, w3.x, u[e].x); u[e].y = fmaf(s.w, w3.y, u[e].y);
            u[e].z = fmaf(s.w, w3.z, u[e].z); u[e].w = fmaf(s.w, w3.w, u[e].w);
        }
    }
    #pragma unroll
    for (int e = 0; e < 4; e++) {
        float4 r;
        r.x = o[e].x + u[e].x; r.y = o[e].y + u[e].y;
        r.z = o[e].z + u[e].z; r.w = o[e].w + u[e].w;
        *(float4*)(out_node + (size_t)(nb + n0 + e) * H + j0) = r;
    }
}

// ---------------------------------------------------------------------------
extern "C" void kernel_launch(void* const* d_in, const int* in_sizes, int n_in,
                              void* d_out, int out_size) {
    const float* x     = (const float*)d_in[0];
    const int*   esrc  = (const int*)  d_in[1];
    const int*   edst  = (const int*)  d_in[2];
    const float* emb   = (const float*)d_in[3];
    const float* ln1g  = (const float*)d_in[4];
    const float* ln1b  = (const float*)d_in[5];
    const float* Wself = (const float*)d_in[6];
    const float* bself = (const float*)d_in[7];
    const float* Wm1   = (const float*)d_in[8];
    const float* bm1   = (const float*)d_in[9];
    const float* Wm2   = (const float*)d_in[10];
    const float* bm2   = (const float*)d_in[11];
    const float* Wg1   = (const float*)d_in[12];
    const float* bg1   = (const float*)d_in[13];
    const float* Wg2   = (const float*)d_in[14];
    const float* bg2   = (const float*)d_in[15];
    const float* Wagg  = (const float*)d_in[16];
    const float* bagg  = (const float*)d_in[17];
    const float* ln2g  = (const float*)d_in[18];
    const float* ln2b  = (const float*)d_in[19];
    const float* Wf1   = (const float*)d_in[20];
    const float* bf1   = (const float*)d_in[21];
    const float* Wf2   = (const float*)d_in[22];
    const float* bf2   = (const float*)d_in[23];

    float* out_node = (float*)d_out;
    float* out_edge = out_node + (size_t)N_NODES * H;

    zero_kernel<<<512, 256>>>();
    ln1_kernel<<<(N_NODES * 32 + 255) / 256, 256>>>(x, ln1g, ln1b);
    edge_kernel<<<E_EDGES / EPB, 128>>>(esrc, edst, emb,
                                        Wm1, bm1, Wm2, bm2,
                                        Wg1, bg1, Wg2, bg2, out_edge);
    node_kernel<<<N_NODES / NPB, 128>>>(x, Wself, bself, Wagg, bagg,
                                        ln2g, ln2b, Wf1, bf1, Wf2, bf2, out_node);
}

// round 2
// speedup vs baseline: 2.0533x; 2.0533x over previous
#include <cuda_runtime.h>
#include <math.h>
#include <stdint.h>

#define N_NODES 50000
#define E_EDGES 600000
#define H 128
#define ED 64

#define EPB 64          // edges per block (E % EPB == 0)
#define TPB 256
#define NPB 16          // nodes per block for node_kernel

#define SIN_S 324       // s_in stride (words); 324%32==4 -> A frags conflict-free
#define ST1_S 132       // t1 stride;   132%32==4 -> A frags conflict-free
#define SW_S  136       // weight chunk stride; 136%32==8 -> B frags conflict-free

// Scratch (device globals: no allocation allowed)
__device__ float g_h[(size_t)N_NODES * H];    // LN1(x)
__device__ float g_agg[(size_t)N_NODES * H];  // segment sum of edge_repr
__device__ float g_deg[N_NODES];              // degree

__device__ __forceinline__ float gelu_exact(float v) {
    return 0.5f * v * (1.0f + erff(v * 0.70710678118654752440f));
}
__device__ __forceinline__ uint32_t f2tf32(float f) {
    uint32_t u;
    asm("cvt.rna.tf32.f32 %0, %1;" : "=r"(u) : "f"(f));
    return u;
}
__device__ __forceinline__ void mma_tf32(float d[4], const uint32_t a[4], const uint32_t b[2]) {
    asm volatile(
        "mma.sync.aligned.m16n8k8.row.col.f32.tf32.tf32.f32 "
        "{%0,%1,%2,%3},{%4,%5,%6,%7},{%8,%9},{%0,%1,%2,%3};"
        : "+f"(d[0]), "+f"(d[1]), "+f"(d[2]), "+f"(d[3])
        : "r"(a[0]), "r"(a[1]), "r"(a[2]), "r"(a[3]), "r"(b[0]), "r"(b[1]));
}

// ---------------------------------------------------------------------------
__global__ void zero_kernel() {
    size_t i = (size_t)blockIdx.x * blockDim.x + threadIdx.x;
    size_t stride = (size_t)gridDim.x * blockDim.x;
    size_t tot = (size_t)N_NODES * H;
    for (size_t k = i; k < tot; k += stride) g_agg[k] = 0.0f;
    for (size_t k = i; k < N_NODES; k += stride) g_deg[k] = 0.0f;
}

// ---------------------------------------------------------------------------
// LN1: one warp per node.
__global__ void ln1_kernel(const float* __restrict__ x,
                           const float* __restrict__ g,
                           const float* __restrict__ b) {
    int warp = (int)((blockIdx.x * blockDim.x + threadIdx.x) >> 5);
    int lane = threadIdx.x & 31;
    if (warp >= N_NODES) return;
    float4 v = *(const float4*)(x + (size_t)warp * H + 4 * lane);
    float s = v.x + v.y + v.z + v.w;
    #pragma unroll
    for (int o = 16; o; o >>= 1) s += __shfl_xor_sync(0xffffffffu, s, o);
    float mu = s * (1.0f / H);
    float dx = v.x - mu, dy = v.y - mu, dz = v.z - mu, dw = v.w - mu;
    float q = dx * dx + dy * dy + dz * dz + dw * dw;
    #pragma unroll
    for (int o = 16; o; o >>= 1) q += __shfl_xor_sync(0xffffffffu, q, o);
    float rstd = rsqrtf(q * (1.0f / H) + 1e-5f);
    float4 gg = *(const float4*)(g + 4 * lane);
    float4 bb = *(const float4*)(b + 4 * lane);
    float4 r;
    r.x = dx * rstd * gg.x + bb.x;
    r.y = dy * rstd * gg.y + bb.y;
    r.z = dz * rstd * gg.z + bb.z;
    r.w = dw * rstd * gg.w + bb.w;
    *(float4*)(g_h + (size_t)warp * H + 4 * lane) = r;
}

// ---------------------------------------------------------------------------
// One GEMM phase: acc[2][4][4] += A[m_base.., colbase+k] * W[k][n]
// A: smem tf32 words, stride strideA. W: global fp32 [K][128], streamed
// through sW in 32-row chunks, software-pipelined (prefetch regs).
__device__ __forceinline__ void gemm_phase(
    const uint32_t* __restrict__ sA, int strideA, int colbase,
    const float* __restrict__ W, int K,
    uint32_t* __restrict__ sW,
    float acc[2][4][4],
    int m_base, int n_base, int gid, int tig, int tid)
{
    int nst = K >> 5;
    float4 pf[4];
    {
        const float4* Wv = (const float4*)W;
        #pragma unroll
        for (int q = 0; q < 4; q++) pf[q] = Wv[tid + TPB * q];
    }
    for (int s = 0; s < nst; ++s) {
        __syncthreads();                           // prior sW consumers done
        #pragma unroll
        for (int q = 0; q < 4; q++) {
            int off = (tid + TPB * q) * 4;         // element offset in 32x128 chunk
            int r = off >> 7, c = off & 127;
            uint32_t* p = sW + r * SW_S + c;
            p[0] = f2tf32(pf[q].x); p[1] = f2tf32(pf[q].y);
            p[2] = f2tf32(pf[q].z); p[3] = f2tf32(pf[q].w);
        }
        __syncthreads();
        if (s + 1 < nst) {
            const float4* Wv = (const float4*)(W + (size_t)(s + 1) * 32 * 128);
            #pragma unroll
            for (int q = 0; q < 4; q++) pf[q] = Wv[tid + TPB * q];
        }
        #pragma unroll
        for (int kc = 0; kc < 4; kc++) {
            int ka = colbase + s * 32 + kc * 8;    // col in A
            int kw = kc * 8;                       // row in sW
            uint32_t a[2][4];
            #pragma unroll
            for (int t = 0; t < 2; t++) {
                int r = m_base + 16 * t + gid;
                a[t][0] = sA[(size_t)r       * strideA + ka + tig];
                a[t][1] = sA[(size_t)(r + 8) * strideA + ka + tig];
                a[t][2] = sA[(size_t)r       * strideA + ka + tig + 4];
                a[t][3] = sA[(size_t)(r + 8) * strideA + ka + tig + 4];
            }
            uint32_t b[4][2];
            #pragma unroll
            for (int j = 0; j < 4; j++) {
                int n0 = n_base + 8 * j + gid;
                b[j][0] = sW[(kw + tig)     * SW_S + n0];
                b[j][1] = sW[(kw + tig + 4) * SW_S + n0];
            }
            #pragma unroll
            for (int t = 0; t < 2; t++)
                #pragma unroll
                for (int j = 0; j < 4; j++)
                    mma_tf32(acc[t][j], a[t], b[j]);
        }
    }
}

// ---------------------------------------------------------------------------
// Edge kernel: 64 edges/CTA, 256 threads, tf32 tensor-core GEMMs.
// Warp tile: 32 edges x 32 cols; warps = 2 (m) x 4 (n-quarter).
extern __shared__ uint32_t smem_raw[];

__global__ void __launch_bounds__(TPB, 1) edge_kernel(
    const int* __restrict__ esrc, const int* __restrict__ edst,
    const float* __restrict__ emb,
    const float* __restrict__ Wm1, const float* __restrict__ bm1,
    const float* __restrict__ Wm2, const float* __restrict__ bm2,
    const float* __restrict__ Wg1, const float* __restrict__ bg1,
    const float* __restrict__ Wg2, const float* __restrict__ bg2,
    float* __restrict__ out_edge)
{
    uint32_t* s_in = smem_raw;                         // [64][324]
    uint32_t* s_t1 = s_in + EPB * SIN_S;               // [64][132]
    uint32_t* s_w  = s_t1 + EPB * ST1_S;               // [32][136]
    float*    s_gp = (float*)(s_w + 32 * SW_S);        // [4][64]
    int*      s_dst = (int*)(s_gp + 4 * EPB);          // [64]
    int*      s_src = s_dst + EPB;                     // [64]

    int tid = threadIdx.x;
    int e_base = blockIdx.x * EPB;
    int lane = tid & 31, warp = tid >> 5;
    int gid = lane >> 2, tig = lane & 3;
    int m_base = (warp & 1) * 32;
    int nq = warp >> 1;
    int n_base = nq * 32;

    if (tid < EPB) {
        int d = edst[e_base + tid];
        s_dst[tid] = d;
        s_src[tid] = esrc[e_base + tid];
        atomicAdd(&g_deg[d], 1.0f);
    }
    __syncthreads();

    // Stage A = [hd(128) | hs(128) | emb(64)] as tf32
    for (int i = tid; i < EPB * 80; i += TPB) {
        int e = i / 80, c = i % 80;                    // c = float4 col
        float4 v;
        if (c < 32)       v = ((const float4*)(g_h + (size_t)s_dst[e] * H))[c];
        else if (c < 64)  v = ((const float4*)(g_h + (size_t)s_src[e] * H))[c - 32];
        else              v = ((const float4*)(emb + (size_t)(e_base + e) * ED))[c - 64];
        uint32_t* p = s_in + (size_t)e * SIN_S + c * 4;
        p[0] = f2tf32(v.x); p[1] = f2tf32(v.y); p[2] = f2tf32(v.z); p[3] = f2tf32(v.w);
    }
    // (gemm_phase starts with __syncthreads — staging is ordered there)

    float acc[2][4][4];

    // ---- gate GEMM g1: [hd||hs||emb] @ Wg1 + bg1, K=320 ----
    #pragma unroll
    for (int t = 0; t < 2; t++)
        #pragma unroll
        for (int j = 0; j < 4; j++) {
            int c0 = n_base + 8 * j + 2 * tig;
            float b0 = __ldg(bg1 + c0), b1 = __ldg(bg1 + c0 + 1);
            acc[t][j][0] = b0; acc[t][j][1] = b1;
            acc[t][j][2] = b0; acc[t][j][3] = b1;
        }
    gemm_phase(s_in, SIN_S, 0, Wg1, 320, s_w, acc, m_base, n_base, gid, tig, tid);

    // gate partials: sum_cols gelu(u)*Wg2 per row
    {
        float p[4] = {0.f, 0.f, 0.f, 0.f};
        #pragma unroll
        for (int j = 0; j < 4; j++) {
            int c0 = n_base + 8 * j + 2 * tig;
            float w0 = __ldg(Wg2 + c0), w1 = __ldg(Wg2 + c0 + 1);
            #pragma unroll
            for (int t = 0; t < 2; t++) {
                p[2 * t + 0] += gelu_exact(acc[t][j][0]) * w0 + gelu_exact(acc[t][j][1]) * w1;
                p[2 * t + 1] += gelu_exact(acc[t][j][2]) * w0 + gelu_exact(acc[t][j][3]) * w1;
            }
        }
        #pragma unroll
        for (int r = 0; r < 4; r++) {
            p[r] += __shfl_xor_sync(0xffffffffu, p[r], 1);
            p[r] += __shfl_xor_sync(0xffffffffu, p[r], 2);
        }
        if (tig == 0) {
            s_gp[nq * EPB + m_base + gid]      = p[0];
            s_gp[nq * EPB + m_base + gid + 8]  = p[1];
            s_gp[nq * EPB + m_base + gid + 16] = p[2];
            s_gp[nq * EPB + m_base + gid + 24] = p[3];
        }
    }

    // ---- message GEMM m1: [hs||emb] @ Wm1 + bm1, K=192 -> gelu -> t1 ----
    #pragma unroll
    for (int t = 0; t < 2; t++)
        #pragma unroll
        for (int j = 0; j < 4; j++) {
            int c0 = n_base + 8 * j + 2 * tig;
            float b0 = __ldg(bm1 + c0), b1 = __ldg(bm1 + c0 + 1);
            acc[t][j][0] = b0; acc[t][j][1] = b1;
            acc[t][j][2] = b0; acc[t][j][3] = b1;
        }
    gemm_phase(s_in, SIN_S, 128, Wm1, 192, s_w, acc, m_base, n_base, gid, tig, tid);
    #pragma unroll
    for (int t = 0; t < 2; t++)
        #pragma unroll
        for (int j = 0; j < 4; j++)
            #pragma unroll
            for (int c = 0; c < 4; c++) {
                int row = m_base + 16 * t + gid + ((c >= 2) ? 8 : 0);
                int col = n_base + 8 * j + 2 * tig + (c & 1);
                s_t1[(size_t)row * ST1_S + col] = f2tf32(gelu_exact(acc[t][j][c]));
            }

    // ---- message GEMM m2: t1 @ Wm2 + bm2, K=128 ----
    #pragma unroll
    for (int t = 0; t < 2; t++)
        #pragma unroll
        for (int j = 0; j < 4; j++) {
            int c0 = n_base + 8 * j + 2 * tig;
            float b0 = __ldg(bm2 + c0), b1 = __ldg(bm2 + c0 + 1);
            acc[t][j][0] = b0; acc[t][j][1] = b1;
            acc[t][j][2] = b0; acc[t][j][3] = b1;
        }
    gemm_phase(s_t1, ST1_S, 0, Wm2, 128, s_w, acc, m_base, n_base, gid, tig, tid);

    // ---- gate, edge_repr = gate*msg, writeout + scatter-add ----
    float bg2v = __ldg(bg2);
    float g4[4];
    #pragma unroll
    for (int r = 0; r < 4; r++) {
        int row = m_base + gid + 8 * r;
        float sgp = s_gp[0 * EPB + row] + s_gp[1 * EPB + row] +
                    s_gp[2 * EPB + row] + s_gp[3 * EPB + row] + bg2v;
        g4[r] = 1.0f / (1.0f + expf(-sgp));
    }
    __syncthreads();   // all m2 reads of s_t1 complete before overwrite
    float* msgf = (float*)s_t1;
    #pragma unroll
    for (int t = 0; t < 2; t++)
        #pragma unroll
        for (int j = 0; j < 4; j++)
            #pragma unroll
            for (int c = 0; c < 4; c++) {
                int r4 = 2 * t + ((c >= 2) ? 1 : 0);
                int row = m_base + 16 * t + gid + ((c >= 2) ? 8 : 0);
                int col = n_base + 8 * j + 2 * tig + (c & 1);
                msgf[(size_t)row * ST1_S + col] = acc[t][j][c] * g4[r4];
            }
    __syncthreads();
    for (int i = tid; i < EPB * 32; i += TPB) {
        int e = i >> 5, c4 = i & 31;
        float4 v = *(float4*)(msgf + (size_t)e * ST1_S + c4 * 4);
        size_t eg = (size_t)(e_base + e);
        *(float4*)(out_edge + eg * H + c4 * 4) = v;
        float* ag = g_agg + (size_t)s_dst[e] * H + c4 * 4;
        atomicAdd(ag + 0, v.x); atomicAdd(ag + 1, v.y);
        atomicAdd(ag + 2, v.z); atomicAdd(ag + 3, v.w);
    }
}

#define EDGE_SMEM_BYTES ((EPB*SIN_S + EPB*ST1_S + 32*SW_S) * 4 + 4*EPB*4 + 2*EPB*4)

// ---------------------------------------------------------------------------
// Node kernel (unchanged from R1): update + residual + LN2 + FFN + residual.
__global__ __launch_bounds__(128) void node_kernel(
    const float* __restrict__ x,
    const float* __restrict__ Wself, const float* __restrict__ bself,
    const float* __restrict__ Wagg,  const float* __restrict__ bagg,
    const float* __restrict__ ln2g,  const float* __restrict__ ln2b,
    const float* __restrict__ Wf1,   const float* __restrict__ bf1,
    const float* __restrict__ Wf2,   const float* __restrict__ bf2,
    float* __restrict__ out_node)
{
    __shared__ float s_h[NPB][H];
    __shared__ float s_a[NPB][H];
    __shared__ float s_t[NPB][2 * H];

    int tid = threadIdx.x, warp = tid >> 5, lane = tid & 31;
    int nb = blockIdx.x * NPB;
    int n0 = warp * 4;
    int j0 = lane * 4;

    for (int i = lane; i < 4 * 32; i += 32) {
        int e = i >> 5, c = i & 31;
        int n = nb + n0 + e;
        *(float4*)(&s_h[n0 + e][c * 4]) = *(const float4*)(g_h + (size_t)n * H + c * 4);
        float invd = 1.0f / fmaxf(g_deg[n], 1.0f);
        float4 a = *(const float4*)(g_agg + (size_t)n * H + c * 4);
        a.x *= invd; a.y *= invd; a.z *= invd; a.w *= invd;
        *(float4*)(&s_a[n0 + e][c * 4]) = a;
    }
    __syncwarp();

    float4 o[4];
    {
        float4 b1 = *(const float4*)(bself + j0);
        float4 b2 = *(const float4*)(bagg + j0);
        float4 bb; bb.x = b1.x + b2.x; bb.y = b1.y + b2.y; bb.z = b1.z + b2.z; bb.w = b1.w + b2.w;
        #pragma unroll
        for (int e = 0; e < 4; e++) o[e] = bb;
    }
    for (int k = 0; k < 128; k += 2) {
        float4 wa0 = *(const float4*)(Wself + (size_t)(k + 0) * H + j0);
        float4 wa1 = *(const float4*)(Wself + (size_t)(k + 1) * H + j0);
        float4 wb0 = *(const float4*)(Wagg + (size_t)(k + 0) * H + j0);
        float4 wb1 = *(const float4*)(Wagg + (size_t)(k + 1) * H + j0);
        #pragma unroll
        for (int e = 0; e < 4; e++) {
            float h0 = s_h[n0 + e][k], h1 = s_h[n0 + e][k + 1];
            float a0 = s_a[n0 + e][k], a1 = s_a[n0 + e][k + 1];
            o[e].x = fmaf(h0, wa0.x, o[e].x); o[e].y = fmaf(h0, wa0.y, o[e].y);
            o[e].z = fmaf(h0, wa0.z, o[e].z); o[e].w = fmaf(h0, wa0.w, o[e].w);
            o[e].x = fmaf(h1, wa1.x, o[e].x); o[e].y = fmaf(h1, wa1.y, o[e].y);
            o[e].z = fmaf(h1, wa1.z, o[e].z); o[e].w = fmaf(h1, wa1.w, o[e].w);
            o[e].x = fmaf(a0, wb0.x, o[e].x); o[e].y = fmaf(a0, wb0.y, o[e].y);
            o[e].z = fmaf(a0, wb0.z, o[e].z); o[e].w = fmaf(a0, wb0.w, o[e].w);
            o[e].x = fmaf(a1, wb1.x, o[e].x); o[e].y = fmaf(a1, wb1.y, o[e].y);
            o[e].z = fmaf(a1, wb1.z, o[e].z); o[e].w = fmaf(a1, wb1.w, o[e].w);
        }
    }
    #pragma unroll
    for (int e = 0; e < 4; e++) {
        float4 xv = *(const float4*)(x + (size_t)(nb + n0 + e) * H + j0);
        o[e].x += xv.x; o[e].y += xv.y; o[e].z += xv.z; o[e].w += xv.w;
    }

    {
        float4 gg = *(const float4*)(ln2g + j0);
        float4 bb = *(const float4*)(ln2b + j0);
        #pragma unroll
        for (int e = 0; e < 4; e++) {
            float s = o[e].x + o[e].y + o[e].z + o[e].w;
            #pragma unroll
            for (int off = 16; off; off >>= 1) s += __shfl_xor_sync(0xffffffffu, s, off);
            float mu = s * (1.0f / H);
            float dx = o[e].x - mu, dy = o[e].y - mu, dz = o[e].z - mu, dw = o[e].w - mu;
            float q = dx * dx + dy * dy + dz * dz + dw * dw;
            #pragma unroll
            for (int off = 16; off; off >>= 1) q += __shfl_xor_sync(0xffffffffu, q, off);
            float rstd = rsqrtf(q * (1.0f / H) + 1e-5f);
            float4 f;
            f.x = dx * rstd * gg.x + bb.x; f.y = dy * rstd * gg.y + bb.y;
            f.z = dz * rstd * gg.z + bb.z; f.w = dw * rstd * gg.w + bb.w;
            *(float4*)(&s_a[n0 + e][j0]) = f;
        }
    }
    __syncwarp();

    int j8 = lane * 8;
    float4 fA[4], fB[4];
    {
        float4 bA = *(const float4*)(bf1 + j8);
        float4 bB = *(const float4*)(bf1 + j8 + 4);
        #pragma unroll
        for (int e = 0; e < 4; e++) { fA[e] = bA; fB[e] = bB; }
    }
    #pragma unroll 2
    for (int k = 0; k < 128; k++) {
        float4 wA = *(const float4*)(Wf1 + (size_t)k * 256 + j8);
        float4 wB = *(const float4*)(Wf1 + (size_t)k * 256 + j8 + 4);
        #pragma unroll
        for (int e = 0; e < 4; e++) {
            float s = s_a[n0 + e][k];
            fA[e].x = fmaf(s, wA.x, fA[e].x); fA[e].y = fmaf(s, wA.y, fA[e].y);
            fA[e].z = fmaf(s, wA.z, fA[e].z); fA[e].w = fmaf(s, wA.w, fA[e].w);
            fB[e].x = fmaf(s, wB.x, fB[e].x); fB[e].y = fmaf(s, wB.y, fB[e].y);
            fB[e].z = fmaf(s, wB.z, fB[e].z); fB[e].w = fmaf(s, wB.w, fB[e].w);
        }
    }
    #pragma unroll
    for (int e = 0; e < 4; e++) {
        float4 tA, tB;
        tA.x = gelu_exact(fA[e].x); tA.y = gelu_exact(fA[e].y);
        tA.z = gelu_exact(fA[e].z); tA.w = gelu_exact(fA[e].w);
        tB.x = gelu_exact(fB[e].x); tB.y = gelu_exact(fB[e].y);
        tB.z = gelu_exact(fB[e].z); tB.w = gelu_exact(fB[e].w);
        *(float4*)(&s_t[n0 + e][j8]) = tA;
        *(float4*)(&s_t[n0 + e][j8 + 4]) = tB;
    }
    __syncwarp();

    float4 u[4];
    {
        float4 bb = *(const float4*)(bf2 + j0);
        #pragma unroll
        for (int e = 0; e < 4; e++) u[e] = bb;
    }
    for (int k = 0; k < 256; k += 4) {
        float4 w0 = *(const float4*)(Wf2 + (size_t)(k + 0) * H + j0);
        float4 w1 = *(const float4*)(Wf2 + (size_t)(k + 1) * H + j0);
        float4 w2 = *(const float4*)(Wf2 + (size_t)(k + 2) * H + j0);
        float4 w3 = *(const float4*)(Wf2 + (size_t)(k + 3) * H + j0);
        #pragma unroll
        for (int e = 0; e < 4; e++) {
            float4 s = *(const float4*)(&s_t[n0 + e][k]);
            u[e].x = fmaf(s.x, w0.x, u[e].x); u[e].y = fmaf(s.x, w0.y, u[e].y);
            u[e].z = fmaf(s.x, w0.z, u[e].z); u[e].w = fmaf(s.x, w0.w, u[e].w);
            u[e].x = fmaf(s.y, w1.x, u[e].x); u[e].y = fmaf(s.y, w1.y, u[e].y);
            u[e].z = fmaf(s.y, w1.z, u[e].z); u[e].w = fmaf(s.y, w1.w, u[e].w);
            u[e].x = fmaf(s.z, w2.x, u[e].x); u[e].y = fmaf(s.z, w2.y, u[e].y);
            u[e].z = fmaf(s.z, w2.z, u[e].z); u[e].w = fmaf(s.z, w2.w, u[e].w);
            u[e].x = fmaf(s.w, w3.x, u[e].x); u[e].y = fmaf(s.w, w3.y, u[e].y);
            u[e].z = fmaf(s.w, w3.z, u[e].z); u[e].w = fmaf(s.w, w3.w, u[e].w);
        }
    }
    #pragma unroll
    for (int e = 0; e < 4; e++) {
        float4 r;
        r.x = o[e].x + u[e].x; r.y = o[e].y + u[e].y;
        r.z = o[e].z + u[e].z; r.w = o[e].w + u[e].w;
        *(float4*)(out_node + (size_t)(nb + n0 + e) * H + j0) = r;
    }
}

// ---------------------------------------------------------------------------
extern "C" void kernel_launch(void* const* d_in, const int* in_sizes, int n_in,
                              void* d_out, int out_size) {
    const float* x     = (const float*)d_in[0];
    const int*   esrc  = (const int*)  d_in[1];
    const int*   edst  = (const int*)  d_in[2];
    const float* emb   = (const float*)d_in[3];
    const float* ln1g  = (const float*)d_in[4];
    const float* ln1b  = (const float*)d_in[5];
    const float* Wself = (const float*)d_in[6];
    const float* bself = (const float*)d_in[7];
    const float* Wm1   = (const float*)d_in[8];
    const float* bm1   = (const float*)d_in[9];
    const float* Wm2   = (const float*)d_in[10];
    const float* bm2   = (const float*)d_in[11];
    const float* Wg1   = (const float*)d_in[12];
    const float* bg1   = (const float*)d_in[13];
    const float* Wg2   = (const float*)d_in[14];
    const float* bg2   = (const float*)d_in[15];
    const float* Wagg  = (const float*)d_in[16];
    const float* bagg  = (const float*)d_in[17];
    const float* ln2g  = (const float*)d_in[18];
    const float* ln2b  = (const float*)d_in[19];
    const float* Wf1   = (const float*)d_in[20];
    const float* bf1   = (const float*)d_in[21];
    const float* Wf2   = (const float*)d_in[22];
    const float* bf2   = (const float*)d_in[23];

    float* out_node = (float*)d_out;
    float* out_edge = out_node + (size_t)N_NODES * H;

    static int smem_set = 0;
    if (!smem_set) {
        cudaFuncSetAttribute(edge_kernel, cudaFuncAttributeMaxDynamicSharedMemorySize,
                             EDGE_SMEM_BYTES);
        smem_set = 1;
    }

    zero_kernel<<<512, 256>>>();
    ln1_kernel<<<(N_NODES * 32 + 255) / 256, 256>>>(x, ln1g, ln1b);
    edge_kernel<<<E_EDGES / EPB, TPB, EDGE_SMEM_BYTES>>>(
        esrc, edst, emb, Wm1, bm1, Wm2, bm2, Wg1, bg1, Wg2, bg2, out_edge);
    node_kernel<<<N_NODES / NPB, 128>>>(x, Wself, bself, Wagg, bagg,
                                        ln2g, ln2b, Wf1, bf1, Wf2, bf2, out_node);
}

// round 6
// speedup vs baseline: 3.0647x; 1.4926x over previous
#include <cuda_runtime.h>
#include <math.h>
#include <stdint.h>

#define N_NODES 50000
#define E_EDGES 600000
#define H 128
#define ED 64

#define EPB 64          // edges per block (E % EPB == 0)
#define TPB 256
#define NPB 16          // nodes per block for node_kernel

#define SIN_S 324       // s_in stride (words); 324%32==4 -> A frags conflict-free
#define SW_S  136       // weight stage stride; 136%32==8 -> B frags conflict-free

// Scratch (device globals: no allocation allowed)
__device__ float g_h[(size_t)N_NODES * H];      // LN1(x), tf32-rounded
__device__ float g_agg[(size_t)N_NODES * H];    // segment sum of edge_repr
__device__ float g_deg[N_NODES];                // degree
__device__ uint32_t g_wg1[320 * 128];           // tf32 weights
__device__ uint32_t g_wm1[192 * 128];
__device__ uint32_t g_wm2[128 * 128];

__device__ __forceinline__ float gelu_exact(float v) {
    return 0.5f * v * (1.0f + erff(v * 0.70710678118654752440f));
}
__device__ __forceinline__ uint32_t f2tf32(float f) {
    uint32_t u;
    asm("cvt.rna.tf32.f32 %0, %1;" : "=r"(u) : "f"(f));
    return u;
}
__device__ __forceinline__ void mma_tf32(float d[4], const uint32_t a[4], const uint32_t b[2]) {
    asm volatile(
        "mma.sync.aligned.m16n8k8.row.col.f32.tf32.tf32.f32 "
        "{%0,%1,%2,%3},{%4,%5,%6,%7},{%8,%9},{%0,%1,%2,%3};"
        : "+f"(d[0]), "+f"(d[1]), "+f"(d[2]), "+f"(d[3])
        : "r"(a[0]), "r"(a[1]), "r"(a[2]), "r"(a[3]), "r"(b[0]), "r"(b[1]));
}
__device__ __forceinline__ void cp_async16(uint32_t saddr, const void* gaddr) {
    asm volatile("cp.async.cg.shared.global [%0], [%1], 16;" :: "r"(saddr), "l"(gaddr));
}

// ---------------------------------------------------------------------------
__global__ void prep_w(const float* __restrict__ Wg1,
                       const float* __restrict__ Wm1,
                       const float* __restrict__ Wm2) {
    int i = blockIdx.x * blockDim.x + threadIdx.x;
    if (i < 320 * 128) g_wg1[i] = f2tf32(Wg1[i]);
    if (i < 192 * 128) g_wm1[i] = f2tf32(Wm1[i]);
    if (i < 128 * 128) g_wm2[i] = f2tf32(Wm2[i]);
}

__global__ void zero_kernel() {
    size_t i = (size_t)blockIdx.x * blockDim.x + threadIdx.x;
    size_t stride = (size_t)gridDim.x * blockDim.x;
    size_t tot = (size_t)N_NODES * H;
    for (size_t k = i; k < tot; k += stride) g_agg[k] = 0.0f;
    for (size_t k = i; k < N_NODES; k += stride) g_deg[k] = 0.0f;
}

// ---------------------------------------------------------------------------
// LN1: one warp per node. Output tf32-rounded (edge A-tiles copy raw bits).
__global__ void ln1_kernel(const float* __restrict__ x,
                           const float* __restrict__ g,
                           const float* __restrict__ b) {
    int warp = (int)((blockIdx.x * blockDim.x + threadIdx.x) >> 5);
    int lane = threadIdx.x & 31;
    if (warp >= N_NODES) return;
    float4 v = *(const float4*)(x + (size_t)warp * H + 4 * lane);
    float s = v.x + v.y + v.z + v.w;
    #pragma unroll
    for (int o = 16; o; o >>= 1) s += __shfl_xor_sync(0xffffffffu, s, o);
    float mu = s * (1.0f / H);
    float dx = v.x - mu, dy = v.y - mu, dz = v.z - mu, dw = v.w - mu;
    float q = dx * dx + dy * dy + dz * dz + dw * dw;
    #pragma unroll
    for (int o = 16; o; o >>= 1) q += __shfl_xor_sync(0xffffffffu, q, o);
    float rstd = rsqrtf(q * (1.0f / H) + 1e-5f);
    float4 gg = *(const float4*)(g + 4 * lane);
    float4 bb = *(const float4*)(b + 4 * lane);
    float4 r;
    r.x = __uint_as_float(f2tf32(dx * rstd * gg.x + bb.x));
    r.y = __uint_as_float(f2tf32(dy * rstd * gg.y + bb.y));
    r.z = __uint_as_float(f2tf32(dz * rstd * gg.z + bb.z));
    r.w = __uint_as_float(f2tf32(dw * rstd * gg.w + bb.w));
    *(float4*)(g_h + (size_t)warp * H + 4 * lane) = r;
}

// ---------------------------------------------------------------------------
// One GEMM phase with cp.async double-buffered weight stages (16 rows each).
// A: smem tf32 words at stride SIN_S. W: pre-converted tf32 global [K][128].
__device__ __forceinline__ void gemm_phase(
    const uint32_t* __restrict__ sA, int colbase,
    const uint32_t* __restrict__ Wg, int K,
    uint32_t* __restrict__ sW, uint32_t sw_saddr,
    float acc[2][4][4],
    int m_base, int n_base, int gid, int tig, int tid)
{
    int nst = K >> 4;
    // prologue: stage 0 -> buf 0
    #pragma unroll
    for (int q = 0; q < 2; q++) {
        int ch = tid + TPB * q;
        int r = ch >> 5, c = (ch & 31) * 4;
        cp_async16(sw_saddr + (r * SW_S + c) * 4, Wg + r * 128 + c);
    }
    asm volatile("cp.async.commit_group;");

    for (int s = 0; s < nst; ++s) {
        __syncthreads();                        // buf (s&1) free of iter s-1 readers
        const uint32_t* buf = sW + (s & 1) * 16 * SW_S;
        if (s + 1 < nst) {
            uint32_t nb_saddr = sw_saddr + (((s + 1) & 1) * 16 * SW_S) * 4;
            const uint32_t* g = Wg + (size_t)(s + 1) * 16 * 128;
            #pragma unroll
            for (int q = 0; q < 2; q++) {
                int ch = tid + TPB * q;
                int r = ch >> 5, c = (ch & 31) * 4;
                cp_async16(nb_saddr + (r * SW_S + c) * 4, g + r * 128 + c);
            }
            asm volatile("cp.async.commit_group;");
            asm volatile("cp.async.wait_group 1;");
        } else {
            asm volatile("cp.async.wait_group 0;");
        }
        __syncthreads();                        // stage s visible to all
        #pragma unroll
        for (int kc = 0; kc < 2; kc++) {
            int ka = colbase + s * 16 + kc * 8;
            int kw = kc * 8;
            uint32_t a[2][4];
            #pragma unroll
            for (int t = 0; t < 2; t++) {
                int r = m_base + 16 * t + gid;
                a[t][0] = sA[(size_t)r       * SIN_S + ka + tig];
                a[t][1] = sA[(size_t)(r + 8) * SIN_S + ka + tig];
                a[t][2] = sA[(size_t)r       * SIN_S + ka + tig + 4];
                a[t][3] = sA[(size_t)(r + 8) * SIN_S + ka + tig + 4];
            }
            uint32_t b[4][2];
            #pragma unroll
            for (int j = 0; j < 4; j++) {
                int n0 = n_base + 8 * j + gid;
                b[j][0] = buf[(kw + tig)     * SW_S + n0];
                b[j][1] = buf[(kw + tig + 4) * SW_S + n0];
            }
            #pragma unroll
            for (int t = 0; t < 2; t++)
                #pragma unroll
                for (int j = 0; j < 4; j++)
                    mma_tf32(acc[t][j], a[t], b[j]);
        }
    }
}

// ---------------------------------------------------------------------------
// Edge kernel: 64 edges/CTA, 256 threads, tf32 tensor-core GEMMs, 2 CTAs/SM.
// Warp tile: 32 edges x 32 cols; warps = 2 (m) x 4 (n-quarter).
extern __shared__ uint32_t smem_raw[];

__global__ void __launch_bounds__(TPB, 2) edge_kernel(
    const int* __restrict__ esrc, const int* __restrict__ edst,
    const float* __restrict__ emb,
    const float* __restrict__ bm1, const float* __restrict__ bm2,
    const float* __restrict__ bg1,
    const float* __restrict__ Wg2, const float* __restrict__ bg2,
    float* __restrict__ out_edge)
{
    uint32_t* s_in = smem_raw;                         // [64][324]
    uint32_t* s_w  = s_in + EPB * SIN_S;               // [2][16][136]
    float*    s_gp = (float*)(s_w + 2 * 16 * SW_S);    // [4][64]
    int*      s_dst = (int*)(s_gp + 4 * EPB);          // [64]
    int*      s_src = s_dst + EPB;                     // [64]
    uint32_t sw_saddr = (uint32_t)__cvta_generic_to_shared(s_w);

    int tid = threadIdx.x;
    int e_base = blockIdx.x * EPB;
    int lane = tid & 31, warp = tid >> 5;
    int gid = lane >> 2, tig = lane & 3;
    int m_base = (warp & 1) * 32;
    int nq = warp >> 1;
    int n_base = nq * 32;

    if (tid < EPB) {
        int d = edst[e_base + tid];
        s_dst[tid] = d;
        s_src[tid] = esrc[e_base + tid];
        atomicAdd(&g_deg[d], 1.0f);
    }
    __syncthreads();

    // Stage A = [hd(128) | hs(128) | emb(64)]; h already tf32 bits, emb cvt here
    for (int i = tid; i < EPB * 80; i += TPB) {
        int e = i / 80, c = i % 80;                    // c = float4 col
        uint32_t* p = s_in + (size_t)e * SIN_S + c * 4;
        if (c < 64) {
            const uint4* src = (c < 32)
                ? (const uint4*)(g_h + (size_t)s_dst[e] * H) + c
                : (const uint4*)(g_h + (size_t)s_src[e] * H) + (c - 32);
            *(uint4*)p = *src;
        } else {
            float4 v = ((const float4*)(emb + (size_t)(e_base + e) * ED))[c - 64];
            p[0] = f2tf32(v.x); p[1] = f2tf32(v.y);
            p[2] = f2tf32(v.z); p[3] = f2tf32(v.w);
        }
    }
    // gemm_phase starts with __syncthreads — staging ordered there

    float acc[2][4][4];

    // ---- gate GEMM g1: [hd||hs||emb] @ Wg1 + bg1, K=320 ----
    #pragma unroll
    for (int t = 0; t < 2; t++)
        #pragma unroll
        for (int j = 0; j < 4; j++) {
            int c0 = n_base + 8 * j + 2 * tig;
            float b0 = __ldg(bg1 + c0), b1 = __ldg(bg1 + c0 + 1);
            acc[t][j][0] = b0; acc[t][j][1] = b1;
            acc[t][j][2] = b0; acc[t][j][3] = b1;
        }
    gemm_phase(s_in, 0, g_wg1, 320, s_w, sw_saddr, acc, m_base, n_base, gid, tig, tid);

    // gate partials: sum_cols gelu(u)*Wg2 per row
    {
        float p[4] = {0.f, 0.f, 0.f, 0.f};
        #pragma unroll
        for (int j = 0; j < 4; j++) {
            int c0 = n_base + 8 * j + 2 * tig;
            float w0 = __ldg(Wg2 + c0), w1 = __ldg(Wg2 + c0 + 1);
            #pragma unroll
            for (int t = 0; t < 2; t++) {
                p[2 * t + 0] += gelu_exact(acc[t][j][0]) * w0 + gelu_exact(acc[t][j][1]) * w1;
                p[2 * t + 1] += gelu_exact(acc[t][j][2]) * w0 + gelu_exact(acc[t][j][3]) * w1;
            }
        }
        #pragma unroll
        for (int r = 0; r < 4; r++) {
            p[r] += __shfl_xor_sync(0xffffffffu, p[r], 1);
            p[r] += __shfl_xor_sync(0xffffffffu, p[r], 2);
        }
        if (tig == 0) {
            s_gp[nq * EPB + m_base + gid]      = p[0];
            s_gp[nq * EPB + m_base + gid + 8]  = p[1];
            s_gp[nq * EPB + m_base + gid + 16] = p[2];
            s_gp[nq * EPB + m_base + gid + 24] = p[3];
        }
    }

    // ---- message GEMM m1: [hs||emb] @ Wm1 + bm1, K=192; t1 -> s_in cols 0..127 ----
    #pragma unroll
    for (int t = 0; t < 2; t++)
        #pragma unroll
        for (int j = 0; j < 4; j++) {
            int c0 = n_base + 8 * j + 2 * tig;
            float b0 = __ldg(bm1 + c0), b1 = __ldg(bm1 + c0 + 1);
            acc[t][j][0] = b0; acc[t][j][1] = b1;
            acc[t][j][2] = b0; acc[t][j][3] = b1;
        }
    gemm_phase(s_in, 128, g_wm1, 192, s_w, sw_saddr, acc, m_base, n_base, gid, tig, tid);
    // hd (cols 0..127) is dead after g1 -> overwrite with t1
    #pragma unroll
    for (int t = 0; t < 2; t++)
        #pragma unroll
        for (int j = 0; j < 4; j++)
            #pragma unroll
            for (int c = 0; c < 4; c++) {
                int row = m_base + 16 * t + gid + ((c >= 2) ? 8 : 0);
                int col = n_base + 8 * j + 2 * tig + (c & 1);
                s_in[(size_t)row * SIN_S + col] = f2tf32(gelu_exact(acc[t][j][c]));
            }

    // ---- message GEMM m2: t1 @ Wm2 + bm2, K=128 ----
    #pragma unroll
    for (int t = 0; t < 2; t++)
        #pragma unroll
        for (int j = 0; j < 4; j++) {
            int c0 = n_base + 8 * j + 2 * tig;
            float b0 = __ldg(bm2 + c0), b1 = __ldg(bm2 + c0 + 1);
            acc[t][j][0] = b0; acc[t][j][1] = b1;
            acc[t][j][2] = b0; acc[t][j][3] = b1;
        }
    gemm_phase(s_in, 0, g_wm2, 128, s_w, sw_saddr, acc, m_base, n_base, gid, tig, tid);

    // ---- gate, edge_repr = gate*msg -> s_in cols 192..319, writeout + scatter ----
    float bg2v = __ldg(bg2);
    float g4[4];
    #pragma unroll
    for (int r = 0; r < 4; r++) {
        int row = m_base + gid + 8 * r;
        float sgp = s_gp[0 * EPB + row] + s_gp[1 * EPB + row] +
                    s_gp[2 * EPB + row] + s_gp[3 * EPB + row] + bg2v;
        g4[r] = 1.0f / (1.0f + expf(-sgp));
    }
    float* msgf = (float*)s_in;      // row r, col c -> [r*SIN_S + 192 + c]
    #pragma unroll
    for (int t = 0; t < 2; t++)
        #pragma unroll
        for (int j = 0; j < 4; j++)
            #pragma unroll
            for (int c = 0; c < 4; c++) {
                int r4 = 2 * t + ((c >= 2) ? 1 : 0);
                int row = m_base + 16 * t + gid + ((c >= 2) ? 8 : 0);
                int col = n_base + 8 * j + 2 * tig + (c & 1);
                msgf[(size_t)row * SIN_S + 192 + col] = acc[t][j][c] * g4[r4];
            }
    __syncthreads();
    for (int i = tid; i < EPB * 32; i += TPB) {
        int e = i >> 5, c4 = i & 31;
        float4 v = *(float4*)(msgf + (size_t)e * SIN_S + 192 + c4 * 4);
        size_t eg = (size_t)(e_base + e);
        *(float4*)(out_edge + eg * H + c4 * 4) = v;
        float* ag = g_agg + (size_t)s_dst[e] * H + c4 * 4;
        atomicAdd(ag + 0, v.x); atomicAdd(ag + 1, v.y);
        atomicAdd(ag + 2, v.z); atomicAdd(ag + 3, v.w);
    }
}

#define EDGE_SMEM_BYTES ((EPB*SIN_S + 2*16*SW_S) * 4 + 4*EPB*4 + 2*EPB*4)

// ---------------------------------------------------------------------------
// Node kernel: update + residual + LN2 + FFN + residual.
__global__ __launch_bounds__(128) void node_kernel(
    const float* __restrict__ x,
    const float* __restrict__ Wself, const float* __restrict__ bself,
    const float* __restrict__ Wagg,  const float* __restrict__ bagg,
    const float* __restrict__ ln2g,  const float* __restrict__ ln2b,
    const float* __restrict__ Wf1,   const float* __restrict__ bf1,
    const float* __restrict__ Wf2,   const float* __restrict__ bf2,
    float* __restrict__ out_node)
{
    __shared__ float s_h[NPB][H];
    __shared__ float s_a[NPB][H];
    __shared__ float s_t[NPB][2 * H];

    int tid = threadIdx.x, warp = tid >> 5, lane = tid & 31;
    int nb = blockIdx.x * NPB;
    int n0 = warp * 4;
    int j0 = lane * 4;

    for (int i = lane; i < 4 * 32; i += 32) {
        int e = i >> 5, c = i & 31;
        int n = nb + n0 + e;
        *(float4*)(&s_h[n0 + e][c * 4]) = *(const float4*)(g_h + (size_t)n * H + c * 4);
        float invd = 1.0f / fmaxf(g_deg[n], 1.0f);
        float4 a = *(const float4*)(g_agg + (size_t)n * H + c * 4);
        a.x *= invd; a.y *= invd; a.z *= invd; a.w *= invd;
        *(float4*)(&s_a[n0 + e][c * 4]) = a;
    }
    __syncwarp();

    float4 o[4];
    {
        float4 b1 = *(const float4*)(bself + j0);
        float4 b2 = *(const float4*)(bagg + j0);
        float4 bb; bb.x = b1.x + b2.x; bb.y = b1.y + b2.y; bb.z = b1.z + b2.z; bb.w = b1.w + b2.w;
        #pragma unroll
        for (int e = 0; e < 4; e++) o[e] = bb;
    }
    for (int k = 0; k < 128; k += 2) {
        float4 wa0 = *(const float4*)(Wself + (size_t)(k + 0) * H + j0);
        float4 wa1 = *(const float4*)(Wself + (size_t)(k + 1) * H + j0);
        float4 wb0 = *(const float4*)(Wagg + (size_t)(k + 0) * H + j0);
        float4 wb1 = *(const float4*)(Wagg + (size_t)(k + 1) * H + j0);
        #pragma unroll
        for (int e = 0; e < 4; e++) {
            float h0 = s_h[n0 + e][k], h1 = s_h[n0 + e][k + 1];
            float a0 = s_a[n0 + e][k], a1 = s_a[n0 + e][k + 1];
            o[e].x = fmaf(h0, wa0.x, o[e].x); o[e].y = fmaf(h0, wa0.y, o[e].y);
            o[e].z = fmaf(h0, wa0.z, o[e].z); o[e].w = fmaf(h0, wa0.w, o[e].w);
            o[e].x = fmaf(h1, wa1.x, o[e].x); o[e].y = fmaf(h1, wa1.y, o[e].y);
            o[e].z = fmaf(h1, wa1.z, o[e].z); o[e].w = fmaf(h1, wa1.w, o[e].w);
            o[e].x = fmaf(a0, wb0.x, o[e].x); o[e].y = fmaf(a0, wb0.y, o[e].y);
            o[e].z = fmaf(a0, wb0.z, o[e].z); o[e].w = fmaf(a0, wb0.w, o[e].w);
            o[e].x = fmaf(a1, wb1.x, o[e].x); o[e].y = fmaf(a1, wb1.y, o[e].y);
            o[e].z = fmaf(a1, wb1.z, o[e].z); o[e].w = fmaf(a1, wb1.w, o[e].w);
        }
    }
    #pragma unroll
    for (int e = 0; e < 4; e++) {
        float4 xv = *(const float4*)(x + (size_t)(nb + n0 + e) * H + j0);
        o[e].x += xv.x; o[e].y += xv.y; o[e].z += xv.z; o[e].w += xv.w;
    }

    {
        float4 gg = *(const float4*)(ln2g + j0);
        float4 bb = *(const float4*)(ln2b + j0);
        #pragma unroll
        for (int e = 0; e < 4; e++) {
            float s = o[e].x + o[e].y + o[e].z + o[e].w;
            #pragma unroll
            for (int off = 16; off; off >>= 1) s += __shfl_xor_sync(0xffffffffu, s, off);
            float mu = s * (1.0f / H);
            float dx = o[e].x - mu, dy = o[e].y - mu, dz = o[e].z - mu, dw = o[e].w - mu;
            float q = dx * dx + dy * dy + dz * dz + dw * dw;
            #pragma unroll
            for (int off = 16; off; off >>= 1) q += __shfl_xor_sync(0xffffffffu, q, off);
            float rstd = rsqrtf(q * (1.0f / H) + 1e-5f);
            float4 f;
            f.x = dx * rstd * gg.x + bb.x; f.y = dy * rstd * gg.y + bb.y;
            f.z = dz * rstd * gg.z + bb.z; f.w = dw * rstd * gg.w + bb.w;
            *(float4*)(&s_a[n0 + e][j0]) = f;
        }
    }
    __syncwarp();

    int j8 = lane * 8;
    float4 fA[4], fB[4];
    {
        float4 bA = *(const float4*)(bf1 + j8);
        float4 bB = *(const float4*)(bf1 + j8 + 4);
        #pragma unroll
        for (int e = 0; e < 4; e++) { fA[e] = bA; fB[e] = bB; }
    }
    #pragma unroll 2
    for (int k = 0; k < 128; k++) {
        float4 wA = *(const float4*)(Wf1 + (size_t)k * 256 + j8);
        float4 wB = *(const float4*)(Wf1 + (size_t)k * 256 + j8 + 4);
        #pragma unroll
        for (int e = 0; e < 4; e++) {
            float s = s_a[n0 + e][k];
            fA[e].x = fmaf(s, wA.x, fA[e].x); fA[e].y = fmaf(s, wA.y, fA[e].y);
            fA[e].z = fmaf(s, wA.z, fA[e].z); fA[e].w = fmaf(s, wA.w, fA[e].w);
            fB[e].x = fmaf(s, wB.x, fB[e].x); fB[e].y = fmaf(s, wB.y, fB[e].y);
            fB[e].z = fmaf(s, wB.z, fB[e].z); fB[e].w = fmaf(s, wB.w, fB[e].w);
        }
    }
    #pragma unroll
    for (int e = 0; e < 4; e++) {
        float4 tA, tB;
        tA.x = gelu_exact(fA[e].x); tA.y = gelu_exact(fA[e].y);
        tA.z = gelu_exact(fA[e].z); tA.w = gelu_exact(fA[e].w);
        tB.x = gelu_exact(fB[e].x); tB.y = gelu_exact(fB[e].y);
        tB.z = gelu_exact(fB[e].z); tB.w = gelu_exact(fB[e].w);
        *(float4*)(&s_t[n0 + e][j8]) = tA;
        *(float4*)(&s_t[n0 + e][j8 + 4]) = tB;
    }
    __syncwarp();

    float4 u[4];
    {
        float4 bb = *(const float4*)(bf2 + j0);
        #pragma unroll
        for (int e = 0; e < 4; e++) u[e] = bb;
    }
    for (int k = 0; k < 256; k += 4) {
        float4 w0 = *(const float4*)(Wf2 + (size_t)(k + 0) * H + j0);
        float4 w1 = *(const float4*)(Wf2 + (size_t)(k + 1) * H + j0);
        float4 w2 = *(const float4*)(Wf2 + (size_t)(k + 2) * H + j0);
        float4 w3 = *(const float4*)(Wf2 + (size_t)(k + 3) * H + j0);
        #pragma unroll
        for (int e = 0; e < 4; e++) {
            float4 s = *(const float4*)(&s_t[n0 + e][k]);
            u[e].x = fmaf(s.x, w0.x, u[e].x); u[e].y = fmaf(s.x, w0.y, u[e].y);
            u[e].z = fmaf(s.x, w0.z, u[e].z); u[e].w = fmaf(s.x, w0.w, u[e].w);
            u[e].x = fmaf(s.y, w1.x, u[e].x); u[e].y = fmaf(s.y, w1.y, u[e].y);
            u[e].z = fmaf(s.y, w1.z, u[e].z); u[e].w = fmaf(s.y, w1.w, u[e].w);
            u[e].x = fmaf(s.z, w2.x, u[e].x); u[e].y = fmaf(s.z, w2.y, u[e].y);
            u[e].z = fmaf(s.z, w2.z, u[e].z); u[e].w = fmaf(s.z, w2.w, u[e].w);
            u[e].x = fmaf(s.w, w3.x, u[e].x); u[e].y = fmaf(s.w, w3.y, u[e].y);
            u[e].z = fmaf(s.w, w3.z, u[e].z); u[e].w = fmaf(s.w, w3.w, u[e].w);
        }
    }
    #pragma unroll
    for (int e = 0; e < 4; e++) {
        float4 r;
        r.x = o[e].x + u[e].x; r.y = o[e].y + u[e].y;
        r.z = o[e].z + u[e].z; r.w = o[e].w + u[e].w;
        *(float4*)(out_node + (size_t)(nb + n0 + e) * H + j0) = r;
    }
}

// ---------------------------------------------------------------------------
extern "C" void kernel_launch(void* const* d_in, const int* in_sizes, int n_in,
                              void* d_out, int out_size) {
    const float* x     = (const float*)d_in[0];
    const int*   esrc  = (const int*)  d_in[1];
    const int*   edst  = (const int*)  d_in[2];
    const float* emb   = (const float*)d_in[3];
    const float* ln1g  = (const float*)d_in[4];
    const float* ln1b  = (const float*)d_in[5];
    const float* Wself = (const float*)d_in[6];
    const float* bself = (const float*)d_in[7];
    const float* Wm1   = (const float*)d_in[8];
    const float* bm1   = (const float*)d_in[9];
    const float* Wm2   = (const float*)d_in[10];
    const float* bm2   = (const float*)d_in[11];
    const float* Wg1   = (const float*)d_in[12];
    const float* bg1   = (const float*)d_in[13];
    const float* Wg2   = (const float*)d_in[14];
    const float* bg2   = (const float*)d_in[15];
    const float* Wagg  = (const float*)d_in[16];
    const float* bagg  = (const float*)d_in[17];
    const float* ln2g  = (const float*)d_in[18];
    const float* ln2b  = (const float*)d_in[19];
    const float* Wf1   = (const float*)d_in[20];
    const float* bf1   = (const float*)d_in[21];
    const float* Wf2   = (const float*)d_in[22];
    const float* bf2   = (const float*)d_in[23];

    float* out_node = (float*)d_out;
    float* out_edge = out_node + (size_t)N_NODES * H;

    static int smem_set = 0;
    if (!smem_set) {
        cudaFuncSetAttribute(edge_kernel, cudaFuncAttributeMaxDynamicSharedMemorySize,
                             EDGE_SMEM_BYTES);
        smem_set = 1;
    }

    prep_w<<<(320 * 128 + 255) / 256, 256>>>(Wg1, Wm1, Wm2);
    zero_kernel<<<512, 256>>>();
    ln1_kernel<<<(N_NODES * 32 + 255) / 256, 256>>>(x, ln1g, ln1b);
    edge_kernel<<<E_EDGES / EPB, TPB, EDGE_SMEM_BYTES>>>(
        esrc, edst, emb, bm1, bm2, bg1, Wg2, bg2, out_edge);
    node_kernel<<<N_NODES / NPB, 128>>>(x, Wself, bself, Wagg, bagg,
                                        ln2g, ln2b, Wf1, bf1, Wf2, bf2, out_node);
}

// round 7
// speedup vs baseline: 3.2681x; 1.0664x over previous
#include <cuda_runtime.h>
#include <math.h>
#include <stdint.h>

#define N_NODES 50000
#define E_EDGES 600000
#define H 128
#define ED 64

#define EPB 64          // edges per block (E % EPB == 0)
#define TPB 256
#define NPB 16          // nodes per block for node_kernel

#define SIN_S 324       // s_in stride (words); rows -> distinct 16B banks for ldmatrix
#define SWT_S 20        // transposed weight stage stride (words); 80B rows, conflict-free

// Scratch (device globals: no allocation allowed)
__device__ float g_h[(size_t)N_NODES * H];      // LN1(x), tf32-rounded
__device__ float g_agg[(size_t)N_NODES * H];    // segment sum of edge_repr
__device__ float g_deg[N_NODES];                // degree
__device__ uint32_t g_wg1t[128 * 320];          // tf32 weights, TRANSPOSED [N][K]
__device__ uint32_t g_wm1t[128 * 192];
__device__ uint32_t g_wm2t[128 * 128];

__device__ __forceinline__ float gelu_exact(float v) {
    return 0.5f * v * (1.0f + erff(v * 0.70710678118654752440f));
}
__device__ __forceinline__ uint32_t f2tf32(float f) {
    uint32_t u;
    asm("cvt.rna.tf32.f32 %0, %1;" : "=r"(u) : "f"(f));
    return u;
}
__device__ __forceinline__ void mma_tf32(float d[4], const uint32_t a[4], const uint32_t b[2]) {
    asm volatile(
        "mma.sync.aligned.m16n8k8.row.col.f32.tf32.tf32.f32 "
        "{%0,%1,%2,%3},{%4,%5,%6,%7},{%8,%9},{%0,%1,%2,%3};"
        : "+f"(d[0]), "+f"(d[1]), "+f"(d[2]), "+f"(d[3])
        : "r"(a[0]), "r"(a[1]), "r"(a[2]), "r"(a[3]), "r"(b[0]), "r"(b[1]));
}
__device__ __forceinline__ void ldsm4(uint32_t r[4], uint32_t addr) {
    asm volatile("ldmatrix.sync.aligned.m8n8.x4.shared.b16 {%0,%1,%2,%3}, [%4];"
                 : "=r"(r[0]), "=r"(r[1]), "=r"(r[2]), "=r"(r[3]) : "r"(addr));
}
__device__ __forceinline__ void cp_async16(uint32_t saddr, const void* gaddr) {
    asm volatile("cp.async.cg.shared.global [%0], [%1], 16;" :: "r"(saddr), "l"(gaddr));
}

// ---------------------------------------------------------------------------
// Pre-convert + transpose weights: [K][128] fp32 -> [128][K] tf32
__global__ void prep_w(const float* __restrict__ Wg1,
                       const float* __restrict__ Wm1,
                       const float* __restrict__ Wm2) {
    int i = blockIdx.x * blockDim.x + threadIdx.x;
    if (i < 320 * 128) { int k = i >> 7, n = i & 127; g_wg1t[n * 320 + k] = f2tf32(Wg1[i]); }
    if (i < 192 * 128) { int k = i >> 7, n = i & 127; g_wm1t[n * 192 + k] = f2tf32(Wm1[i]); }
    if (i < 128 * 128) { int k = i >> 7, n = i & 127; g_wm2t[n * 128 + k] = f2tf32(Wm2[i]); }
}

__global__ void zero_kernel() {
    size_t i = (size_t)blockIdx.x * blockDim.x + threadIdx.x;
    size_t stride = (size_t)gridDim.x * blockDim.x;
    size_t tot = (size_t)N_NODES * H;
    for (size_t k = i; k < tot; k += stride) g_agg[k] = 0.0f;
    for (size_t k = i; k < N_NODES; k += stride) g_deg[k] = 0.0f;
}

// ---------------------------------------------------------------------------
// LN1: one warp per node. Output tf32-rounded (edge A-tiles copy raw bits).
__global__ void ln1_kernel(const float* __restrict__ x,
                           const float* __restrict__ g,
                           const float* __restrict__ b) {
    int warp = (int)((blockIdx.x * blockDim.x + threadIdx.x) >> 5);
    int lane = threadIdx.x & 31;
    if (warp >= N_NODES) return;
    float4 v = *(const float4*)(x + (size_t)warp * H + 4 * lane);
    float s = v.x + v.y + v.z + v.w;
    #pragma unroll
    for (int o = 16; o; o >>= 1) s += __shfl_xor_sync(0xffffffffu, s, o);
    float mu = s * (1.0f / H);
    float dx = v.x - mu, dy = v.y - mu, dz = v.z - mu, dw = v.w - mu;
    float q = dx * dx + dy * dy + dz * dz + dw * dw;
    #pragma unroll
    for (int o = 16; o; o >>= 1) q += __shfl_xor_sync(0xffffffffu, q, o);
    float rstd = rsqrtf(q * (1.0f / H) + 1e-5f);
    float4 gg = *(const float4*)(g + 4 * lane);
    float4 bb = *(const float4*)(b + 4 * lane);
    float4 r;
    r.x = __uint_as_float(f2tf32(dx * rstd * gg.x + bb.x));
    r.y = __uint_as_float(f2tf32(dy * rstd * gg.y + bb.y));
    r.z = __uint_as_float(f2tf32(dz * rstd * gg.z + bb.z));
    r.w = __uint_as_float(f2tf32(dw * rstd * gg.w + bb.w));
    *(float4*)(g_h + (size_t)warp * H + 4 * lane) = r;
}

// ---------------------------------------------------------------------------
// One GEMM phase. A fragments via ldmatrix from s_in (per-thread base addr,
// colbase folded in). B: transposed tf32 weights [128][K] streamed through a
// double-buffered [128][SWT_S] smem stage via cp.async; fragments via ldmatrix.
__device__ __forceinline__ void gemm_phase(
    uint32_t a_base,                           // per-thread A ldmatrix byte addr (incl colbase)
    const uint32_t* __restrict__ WT, int K,    // [128][K] tf32, k-contiguous
    uint32_t sw_saddr, uint32_t b_off,         // per-thread B ldmatrix byte offset in buffer
    float acc[2][4][4], int tid)
{
    int nst = K >> 4;
    #pragma unroll
    for (int q = 0; q < 2; q++) {
        int ch = tid + TPB * q;
        int n = ch >> 2, c4 = (ch & 3) << 2;
        cp_async16(sw_saddr + (n * SWT_S + c4) * 4, WT + (size_t)n * K + c4);
    }
    asm volatile("cp.async.commit_group;");

    for (int s = 0; s < nst; ++s) {
        __syncthreads();                       // buf (s&1) free of iter s-1 readers
        uint32_t buf = sw_saddr + (s & 1) * (128 * SWT_S * 4);
        if (s + 1 < nst) {
            uint32_t nb = sw_saddr + ((s + 1) & 1) * (128 * SWT_S * 4);
            const uint32_t* g = WT + (size_t)(s + 1) * 16;
            #pragma unroll
            for (int q = 0; q < 2; q++) {
                int ch = tid + TPB * q;
                int n = ch >> 2, c4 = (ch & 3) << 2;
                cp_async16(nb + (n * SWT_S + c4) * 4, g + (size_t)n * K + c4);
            }
            asm volatile("cp.async.commit_group;");
            asm volatile("cp.async.wait_group 1;");
        } else {
            asm volatile("cp.async.wait_group 0;");
        }
        __syncthreads();                       // stage s visible to all
        #pragma unroll
        for (int kc = 0; kc < 2; kc++) {
            uint32_t aaddr = a_base + (s * 16 + kc * 8) * 4;
            uint32_t a0[4], a1[4], b01[4], b23[4];
            ldsm4(a0, aaddr);
            ldsm4(a1, aaddr + 16 * SIN_S * 4);
            uint32_t baddr = buf + b_off + kc * 8 * 4;
            ldsm4(b01, baddr);
            ldsm4(b23, baddr + 16 * SWT_S * 4);
            mma_tf32(acc[0][0], a0, b01);     mma_tf32(acc[0][1], a0, b01 + 2);
            mma_tf32(acc[0][2], a0, b23);     mma_tf32(acc[0][3], a0, b23 + 2);
            mma_tf32(acc[1][0], a1, b01);     mma_tf32(acc[1][1], a1, b01 + 2);
            mma_tf32(acc[1][2], a1, b23);     mma_tf32(acc[1][3], a1, b23 + 2);
        }
    }
}

// ---------------------------------------------------------------------------
// Edge kernel: 64 edges/CTA, 256 threads, tf32 tensor-core GEMMs, 2 CTAs/SM.
// Warp tile: 32 edges x 32 cols; warps = 2 (m) x 4 (n-quarter).
extern __shared__ uint32_t smem_raw[];

__global__ void __launch_bounds__(TPB, 2) edge_kernel(
    const int* __restrict__ esrc, const int* __restrict__ edst,
    const float* __restrict__ emb,
    const float* __restrict__ bm1, const float* __restrict__ bm2,
    const float* __restrict__ bg1,
    const float* __restrict__ Wg2, const float* __restrict__ bg2,
    float* __restrict__ out_edge)
{
    uint32_t* s_in = smem_raw;                         // [64][324]
    uint32_t* s_w  = s_in + EPB * SIN_S;               // [2][128][20]
    float*    s_gp = (float*)(s_w + 2 * 128 * SWT_S);  // [4][64]
    int*      s_dst = (int*)(s_gp + 4 * EPB);          // [64]
    int*      s_src = s_dst + EPB;                     // [64]
    uint32_t sw_saddr  = (uint32_t)__cvta_generic_to_shared(s_w);
    uint32_t sin_saddr = (uint32_t)__cvta_generic_to_shared(s_in);

    int tid = threadIdx.x;
    int e_base = blockIdx.x * EPB;
    int lane = tid & 31, warp = tid >> 5;
    int gid = lane >> 2, tig = lane & 3;
    int m_base = (warp & 1) * 32;
    int nq = warp >> 1;
    int n_base = nq * 32;

    // per-thread ldmatrix addresses
    uint32_t a_thread = sin_saddr +
        ((m_base + (lane & 15)) * SIN_S + ((lane >> 4) << 2)) * 4;
    int g8 = lane >> 3;
    int nr = n_base + ((g8 >> 1) << 3) + (lane & 7);
    uint32_t b_off = (nr * SWT_S + ((g8 & 1) << 2)) * 4;

    if (tid < EPB) {
        int d = edst[e_base + tid];
        s_dst[tid] = d;
        s_src[tid] = esrc[e_base + tid];
        atomicAdd(&g_deg[d], 1.0f);
    }
    __syncthreads();

    // Stage A = [hd(128) | hs(128) | emb(64)]; h already tf32 bits, emb cvt here
    for (int i = tid; i < EPB * 80; i += TPB) {
        int e = i / 80, c = i % 80;                    // c = float4 col
        uint32_t* p = s_in + (size_t)e * SIN_S + c * 4;
        if (c < 64) {
            const uint4* src = (c < 32)
                ? (const uint4*)(g_h + (size_t)s_dst[e] * H) + c
                : (const uint4*)(g_h + (size_t)s_src[e] * H) + (c - 32);
            *(uint4*)p = *src;
        } else {
            float4 v = ((const float4*)(emb + (size_t)(e_base + e) * ED))[c - 64];
            p[0] = f2tf32(v.x); p[1] = f2tf32(v.y);
            p[2] = f2tf32(v.z); p[3] = f2tf32(v.w);
        }
    }
    // gemm_phase starts with __syncthreads — staging ordered there

    float acc[2][4][4];

    // ---- gate GEMM g1: [hd||hs||emb] @ Wg1 + bg1, K=320 ----
    #pragma unroll
    for (int t = 0; t < 2; t++)
        #pragma unroll
        for (int j = 0; j < 4; j++) {
            int c0 = n_base + 8 * j + 2 * tig;
            float b0 = __ldg(bg1 + c0), b1 = __ldg(bg1 + c0 + 1);
            acc[t][j][0] = b0; acc[t][j][1] = b1;
            acc[t][j][2] = b0; acc[t][j][3] = b1;
        }
    gemm_phase(a_thread, g_wg1t, 320, sw_saddr, b_off, acc, tid);

    // gate partials: sum_cols gelu(u)*Wg2 per row
    {
        float p[4] = {0.f, 0.f, 0.f, 0.f};
        #pragma unroll
        for (int j = 0; j < 4; j++) {
            int c0 = n_base + 8 * j + 2 * tig;
            float w0 = __ldg(Wg2 + c0), w1 = __ldg(Wg2 + c0 + 1);
            #pragma unroll
            for (int t = 0; t < 2; t++) {
                p[2 * t + 0] += gelu_exact(acc[t][j][0]) * w0 + gelu_exact(acc[t][j][1]) * w1;
                p[2 * t + 1] += gelu_exact(acc[t][j][2]) * w0 + gelu_exact(acc[t][j][3]) * w1;
            }
        }
        #pragma unroll
        for (int r = 0; r < 4; r++) {
            p[r] += __shfl_xor_sync(0xffffffffu, p[r], 1);
            p[r] += __shfl_xor_sync(0xffffffffu, p[r], 2);
        }
        if (tig == 0) {
            s_gp[nq * EPB + m_base + gid]      = p[0];
            s_gp[nq * EPB + m_base + gid + 8]  = p[1];
            s_gp[nq * EPB + m_base + gid + 16] = p[2];
            s_gp[nq * EPB + m_base + gid + 24] = p[3];
        }
    }

    // ---- message GEMM m1: [hs||emb] @ Wm1 + bm1, K=192; t1 -> s_in cols 0..127 ----
    #pragma unroll
    for (int t = 0; t < 2; t++)
        #pragma unroll
        for (int j = 0; j < 4; j++) {
            int c0 = n_base + 8 * j + 2 * tig;
            float b0 = __ldg(bm1 + c0), b1 = __ldg(bm1 + c0 + 1);
            acc[t][j][0] = b0; acc[t][j][1] = b1;
            acc[t][j][2] = b0; acc[t][j][3] = b1;
        }
    gemm_phase(a_thread + 128 * 4, g_wm1t, 192, sw_saddr, b_off, acc, tid);
    // hd (cols 0..127) is dead after g1 -> overwrite with t1
    #pragma unroll
    for (int t = 0; t < 2; t++)
        #pragma unroll
        for (int j = 0; j < 4; j++)
            #pragma unroll
            for (int c = 0; c < 4; c++) {
                int row = m_base + 16 * t + gid + ((c >= 2) ? 8 : 0);
                int col = n_base + 8 * j + 2 * tig + (c & 1);
                s_in[(size_t)row * SIN_S + col] = f2tf32(gelu_exact(acc[t][j][c]));
            }

    // ---- message GEMM m2: t1 @ Wm2 + bm2, K=128 ----
    #pragma unroll
    for (int t = 0; t < 2; t++)
        #pragma unroll
        for (int j = 0; j < 4; j++) {
            int c0 = n_base + 8 * j + 2 * tig;
            float b0 = __ldg(bm2 + c0), b1 = __ldg(bm2 + c0 + 1);
            acc[t][j][0] = b0; acc[t][j][1] = b1;
            acc[t][j][2] = b0; acc[t][j][3] = b1;
        }
    gemm_phase(a_thread, g_wm2t, 128, sw_saddr, b_off, acc, tid);

    // ---- gate, edge_repr = gate*msg -> s_in cols 192..319, writeout + scatter ----
    float bg2v = __ldg(bg2);
    float g4[4];
    #pragma unroll
    for (int r = 0; r < 4; r++) {
        int row = m_base + gid + 8 * r;
        float sgp = s_gp[0 * EPB + row] + s_gp[1 * EPB + row] +
                    s_gp[2 * EPB + row] + s_gp[3 * EPB + row] + bg2v;
        g4[r] = 1.0f / (1.0f + expf(-sgp));
    }
    float* msgf = (float*)s_in;      // row r, col c -> [r*SIN_S + 192 + c]
    #pragma unroll
    for (int t = 0; t < 2; t++)
        #pragma unroll
        for (int j = 0; j < 4; j++)
            #pragma unroll
            for (int c = 0; c < 4; c++) {
                int r4 = 2 * t + ((c >= 2) ? 1 : 0);
                int row = m_base + 16 * t + gid + ((c >= 2) ? 8 : 0);
                int col = n_base + 8 * j + 2 * tig + (c & 1);
                msgf[(size_t)row * SIN_S + 192 + col] = acc[t][j][c] * g4[r4];
            }
    __syncthreads();
    for (int i = tid; i < EPB * 32; i += TPB) {
        int e = i >> 5, c4 = i & 31;
        float4 v = *(float4*)(msgf + (size_t)e * SIN_S + 192 + c4 * 4);
        size_t eg = (size_t)(e_base + e);
        *(float4*)(out_edge + eg * H + c4 * 4) = v;
        float* ag = g_agg + (size_t)s_dst[e] * H + c4 * 4;
        asm volatile("red.global.add.v4.f32 [%0], {%1,%2,%3,%4};"
                     :: "l"(ag), "f"(v.x), "f"(v.y), "f"(v.z), "f"(v.w) : "memory");
    }
}

#define EDGE_SMEM_BYTES ((EPB*SIN_S + 2*128*SWT_S) * 4 + 4*EPB*4 + 2*EPB*4)

// ---------------------------------------------------------------------------
// Node kernel: update + residual + LN2 + FFN + residual.
__global__ __launch_bounds__(128) void node_kernel(
    const float* __restrict__ x,
    const float* __restrict__ Wself, const float* __restrict__ bself,
    const float* __restrict__ Wagg,  const float* __restrict__ bagg,
    const float* __restrict__ ln2g,  const float* __restrict__ ln2b,
    const float* __restrict__ Wf1,   const float* __restrict__ bf1,
    const float* __restrict__ Wf2,   const float* __restrict__ bf2,
    float* __restrict__ out_node)
{
    __shared__ float s_h[NPB][H];
    __shared__ float s_a[NPB][H];
    __shared__ float s_t[NPB][2 * H];

    int tid = threadIdx.x, warp = tid >> 5, lane = tid & 31;
    int nb = blockIdx.x * NPB;
    int n0 = warp * 4;
    int j0 = lane * 4;

    for (int i = lane; i < 4 * 32; i += 32) {
        int e = i >> 5, c = i & 31;
        int n = nb + n0 + e;
        *(float4*)(&s_h[n0 + e][c * 4]) = *(const float4*)(g_h + (size_t)n * H + c * 4);
        float invd = 1.0f / fmaxf(g_deg[n], 1.0f);
        float4 a = *(const float4*)(g_agg + (size_t)n * H + c * 4);
        a.x *= invd; a.y *= invd; a.z *= invd; a.w *= invd;
        *(float4*)(&s_a[n0 + e][c * 4]) = a;
    }
    __syncwarp();

    float4 o[4];
    {
        float4 b1 = *(const float4*)(bself + j0);
        float4 b2 = *(const float4*)(bagg + j0);
        float4 bb; bb.x = b1.x + b2.x; bb.y = b1.y + b2.y; bb.z = b1.z + b2.z; bb.w = b1.w + b2.w;
        #pragma unroll
        for (int e = 0; e < 4; e++) o[e] = bb;
    }
    for (int k = 0; k < 128; k += 2) {
        float4 wa0 = *(const float4*)(Wself + (size_t)(k + 0) * H + j0);
        float4 wa1 = *(const float4*)(Wself + (size_t)(k + 1) * H + j0);
        float4 wb0 = *(const float4*)(Wagg + (size_t)(k + 0) * H + j0);
        float4 wb1 = *(const float4*)(Wagg + (size_t)(k + 1) * H + j0);
        #pragma unroll
        for (int e = 0; e < 4; e++) {
            float h0 = s_h[n0 + e][k], h1 = s_h[n0 + e][k + 1];
            float a0 = s_a[n0 + e][k], a1 = s_a[n0 + e][k + 1];
            o[e].x = fmaf(h0, wa0.x, o[e].x); o[e].y = fmaf(h0, wa0.y, o[e].y);
            o[e].z = fmaf(h0, wa0.z, o[e].z); o[e].w = fmaf(h0, wa0.w, o[e].w);
            o[e].x = fmaf(h1, wa1.x, o[e].x); o[e].y = fmaf(h1, wa1.y, o[e].y);
            o[e].z = fmaf(h1, wa1.z, o[e].z); o[e].w = fmaf(h1, wa1.w, o[e].w);
            o[e].x = fmaf(a0, wb0.x, o[e].x); o[e].y = fmaf(a0, wb0.y, o[e].y);
            o[e].z = fmaf(a0, wb0.z, o[e].z); o[e].w = fmaf(a0, wb0.w, o[e].w);
            o[e].x = fmaf(a1, wb1.x, o[e].x); o[e].y = fmaf(a1, wb1.y, o[e].y);
            o[e].z = fmaf(a1, wb1.z, o[e].z); o[e].w = fmaf(a1, wb1.w, o[e].w);
        }
    }
    #pragma unroll
    for (int e = 0; e < 4; e++) {
        float4 xv = *(const float4*)(x + (size_t)(nb + n0 + e) * H + j0);
        o[e].x += xv.x; o[e].y += xv.y; o[e].z += xv.z; o[e].w += xv.w;
    }

    {
        float4 gg = *(const float4*)(ln2g + j0);
        float4 bb = *(const float4*)(ln2b + j0);
        #pragma unroll
        for (int e = 0; e < 4; e++) {
            float s = o[e].x + o[e].y + o[e].z + o[e].w;
            #pragma unroll
            for (int off = 16; off; off >>= 1) s += __shfl_xor_sync(0xffffffffu, s, off);
            float mu = s * (1.0f / H);
            float dx = o[e].x - mu, dy = o[e].y - mu, dz = o[e].z - mu, dw = o[e].w - mu;
            float q = dx * dx + dy * dy + dz * dz + dw * dw;
            #pragma unroll
            for (int off = 16; off; off >>= 1) q += __shfl_xor_sync(0xffffffffu, q, off);
            float rstd = rsqrtf(q * (1.0f / H) + 1e-5f);
            float4 f;
            f.x = dx * rstd * gg.x + bb.x; f.y = dy * rstd * gg.y + bb.y;
            f.z = dz * rstd * gg.z + bb.z; f.w = dw * rstd * gg.w + bb.w;
            *(float4*)(&s_a[n0 + e][j0]) = f;
        }
    }
    __syncwarp();

    int j8 = lane * 8;
    float4 fA[4], fB[4];
    {
        float4 bA = *(const float4*)(bf1 + j8);
        float4 bB = *(const float4*)(bf1 + j8 + 4);
        #pragma unroll
        for (int e = 0; e < 4; e++) { fA[e] = bA; fB[e] = bB; }
    }
    #pragma unroll 2
    for (int k = 0; k < 128; k++) {
        float4 wA = *(const float4*)(Wf1 + (size_t)k * 256 + j8);
        float4 wB = *(const float4*)(Wf1 + (size_t)k * 256 + j8 + 4);
        #pragma unroll
        for (int e = 0; e < 4; e++) {
            float s = s_a[n0 + e][k];
            fA[e].x = fmaf(s, wA.x, fA[e].x); fA[e].y = fmaf(s, wA.y, fA[e].y);
            fA[e].z = fmaf(s, wA.z, fA[e].z); fA[e].w = fmaf(s, wA.w, fA[e].w);
            fB[e].x = fmaf(s, wB.x, fB[e].x); fB[e].y = fmaf(s, wB.y, fB[e].y);
            fB[e].z = fmaf(s, wB.z, fB[e].z); fB[e].w = fmaf(s, wB.w, fB[e].w);
        }
    }
    #pragma unroll
    for (int e = 0; e < 4; e++) {
        float4 tA, tB;
        tA.x = gelu_exact(fA[e].x); tA.y = gelu_exact(fA[e].y);
        tA.z = gelu_exact(fA[e].z); tA.w = gelu_exact(fA[e].w);
        tB.x = gelu_exact(fB[e].x); tB.y = gelu_exact(fB[e].y);
        tB.z = gelu_exact(fB[e].z); tB.w = gelu_exact(fB[e].w);
        *(float4*)(&s_t[n0 + e][j8]) = tA;
        *(float4*)(&s_t[n0 + e][j8 + 4]) = tB;
    }
    __syncwarp();

    float4 u[4];
    {
        float4 bb = *(const float4*)(bf2 + j0);
        #pragma unroll
        for (int e = 0; e < 4; e++) u[e] = bb;
    }
    for (int k = 0; k < 256; k += 4) {
        float4 w0 = *(const float4*)(Wf2 + (size_t)(k + 0) * H + j0);
        float4 w1 = *(const float4*)(Wf2 + (size_t)(k + 1) * H + j0);
        float4 w2 = *(const float4*)(Wf2 + (size_t)(k + 2) * H + j0);
        float4 w3 = *(const float4*)(Wf2 + (size_t)(k + 3) * H + j0);
        #pragma unroll
        for (int e = 0; e < 4; e++) {
            float4 s = *(const float4*)(&s_t[n0 + e][k]);
            u[e].x = fmaf(s.x, w0.x, u[e].x); u[e].y = fmaf(s.x, w0.y, u[e].y);
            u[e].z = fmaf(s.x, w0.z, u[e].z); u[e].w = fmaf(s.x, w0.w, u[e].w);
            u[e].x = fmaf(s.y, w1.x, u[e].x); u[e].y = fmaf(s.y, w1.y, u[e].y);
            u[e].z = fmaf(s.y, w1.z, u[e].z); u[e].w = fmaf(s.y, w1.w, u[e].w);
            u[e].x = fmaf(s.z, w2.x, u[e].x); u[e].y = fmaf(s.z, w2.y, u[e].y);
            u[e].z = fmaf(s.z, w2.z, u[e].z); u[e].w = fmaf(s.z, w2.w, u[e].w);
            u[e].x = fmaf(s.w, w3.x, u[e].x); u[e].y = fmaf(s.w, w3.y, u[e].y);
            u[e].z = fmaf(s.w, w3.z, u[e].z); u[e].w = fmaf(s.w, w3.w, u[e].w);
        }
    }
    #pragma unroll
    for (int e = 0; e < 4; e++) {
        float4 r;
        r.x = o[e].x + u[e].x; r.y = o[e].y + u[e].y;
        r.z = o[e].z + u[e].z; r.w = o[e].w + u[e].w;
        *(float4*)(out_node + (size_t)(nb + n0 + e) * H + j0) = r;
    }
}

// ---------------------------------------------------------------------------
extern "C" void kernel_launch(void* const* d_in, const int* in_sizes, int n_in,
                              void* d_out, int out_size) {
    const float* x     = (const float*)d_in[0];
    const int*   esrc  = (const int*)  d_in[1];
    const int*   edst  = (const int*)  d_in[2];
    const float* emb   = (const float*)d_in[3];
    const float* ln1g  = (const float*)d_in[4];
    const float* ln1b  = (const float*)d_in[5];
    const float* Wself = (const float*)d_in[6];
    const float* bself = (const float*)d_in[7];
    const float* Wm1   = (const float*)d_in[8];
    const float* bm1   = (const float*)d_in[9];
    const float* Wm2   = (const float*)d_in[10];
    const float* bm2   = (const float*)d_in[11];
    const float* Wg1   = (const float*)d_in[12];
    const float* bg1   = (const float*)d_in[13];
    const float* Wg2   = (const float*)d_in[14];
    const float* bg2   = (const float*)d_in[15];
    const float* Wagg  = (const float*)d_in[16];
    const float* bagg  = (const float*)d_in[17];
    const float* ln2g  = (const float*)d_in[18];
    const float* ln2b  = (const float*)d_in[19];
    const float* Wf1   = (const float*)d_in[20];
    const float* bf1   = (const float*)d_in[21];
    const float* Wf2   = (const float*)d_in[22];
    const float* bf2   = (const float*)d_in[23];

    float* out_node = (float*)d_out;
    float* out_edge = out_node + (size_t)N_NODES * H;

    static int smem_set = 0;
    if (!smem_set) {
        cudaFuncSetAttribute(edge_kernel, cudaFuncAttributeMaxDynamicSharedMemorySize,
                             EDGE_SMEM_BYTES);
        smem_set = 1;
    }

    prep_w<<<(320 * 128 + 255) / 256, 256>>>(Wg1, Wm1, Wm2);
    zero_kernel<<<512, 256>>>();
    ln1_kernel<<<(N_NODES * 32 + 255) / 256, 256>>>(x, ln1g, ln1b);
    edge_kernel<<<E_EDGES / EPB, TPB, EDGE_SMEM_BYTES>>>(
        esrc, edst, emb, bm1, bm2, bg1, Wg2, bg2, out_edge);
    node_kernel<<<N_NODES / NPB, 128>>>(x, Wself, bself, Wagg, bagg,
                                        ln2g, ln2b, Wf1, bf1, Wf2, bf2, out_node);
}